// round 4
// baseline (speedup 1.0000x reference)
#include <cuda_runtime.h>
#include <math.h>
#include <stdint.h>

#define D_MODEL 768
#define D_INNER 1536
#define NBATCH 4
#define LSEQ 2048
#define MROWS (NBATCH * LSEQ)      // 8192
#define DT_RANK 48
#define D_STATE 16
#define XDBL_N (DT_RANK + 2 * D_STATE)   // 80

// -------- scratch (device globals; no allocation allowed) --------
__device__ __align__(16) float g_xr[(size_t)MROWS * 2 * D_INNER];   // in_proj out [8192,3072]
__device__ __align__(16) float g_h[(size_t)MROWS * D_INNER];        // conv+silu out
__device__ __align__(16) float g_xdbl[(size_t)MROWS * XDBL_N];      // x_proj out [8192,80]
__device__ __align__(16) float g_dtin[(size_t)MROWS * DT_RANK];     // dt cols, tf32-rounded
__device__ __align__(16) float g_delta[(size_t)MROWS * D_INNER];    // softplus(dt_proj)
__device__ __align__(16) float g_y[(size_t)MROWS * D_INNER];        // scan out (tf32-rounded)
// tf32-rounded operand copies
__device__ __align__(16) float g_xt[(size_t)MROWS * D_MODEL];
__device__ __align__(16) float g_wint[(size_t)2 * D_INNER * D_MODEL];
__device__ __align__(16) float g_wdtt[(size_t)D_INNER * DT_RANK];
__device__ __align__(16) float g_woutt[(size_t)D_MODEL * D_INNER];

__device__ __forceinline__ float siluf(float v) { return v / (1.f + __expf(-v)); }
__device__ __forceinline__ float softplusf(float v) {
    return v > 20.f ? v : log1pf(__expf(v));
}
__device__ __forceinline__ unsigned f2tf32(float f) {
    unsigned u;
    asm("cvt.rna.tf32.f32 %0, %1;" : "=r"(u) : "f"(f));
    return u;
}
__device__ __forceinline__ void cp16(uint32_t s, const void* g) {
    asm volatile("cp.async.cg.shared.global [%0], [%1], 16;" :: "r"(s), "l"(g));
}
#define CP_COMMIT() asm volatile("cp.async.commit_group;" ::: "memory")
#define CP_WAIT(n)  asm volatile("cp.async.wait_group %0;" :: "n"(n) : "memory")

// ============================================================================
// Elementwise fp32 -> tf32(rna)-rounded copy (vectorized).
// ============================================================================
__global__ __launch_bounds__(256) void cvt_tf32_kernel(
    const float4* __restrict__ src, float4* __restrict__ dst, int n4)
{
    int i = blockIdx.x * 256 + threadIdx.x;
    if (i < n4) {
        float4 v = src[i];
        v.x = __uint_as_float(f2tf32(v.x));
        v.y = __uint_as_float(f2tf32(v.y));
        v.z = __uint_as_float(f2tf32(v.z));
        v.w = __uint_as_float(f2tf32(v.w));
        dst[i] = v;
    }
}

// ============================================================================
// TF32 tensor-core NT GEMM, cp.async 4-stage pipeline.
// C[M,N] = A[M,K]*B[N,K]^T (+bias,+softplus). A,B pre-rounded to tf32 bits.
// Req: M%128==0, N%128==0, K%16==0, rows 16B-aligned (lda,ldb%4==0).
// Block 128x128, BK=16, 256 thr, 8 warps 2(M)x4(N), warp tile 64x32,
// mma.sync.m16n8k8.tf32; smem XOR-swizzle c4 ^= (row>>1)&3.
// ============================================================================
__global__ __launch_bounds__(256, 2) void tf32_gemm_ca(
    int M, int N, int K,
    const float* __restrict__ A, int lda,
    const float* __restrict__ B, int ldb,
    const float* __restrict__ bias,
    float* __restrict__ C, int act)
{
    extern __shared__ __align__(16) char sm[];   // 4 stages: A st*8192 ; B 32768+st*8192

    const int tid = threadIdx.x;
    const int lane = tid & 31;
    const int warp = tid >> 5;
    const int wm = (warp & 1) * 64;
    const int wn = (warp >> 1) * 32;
    const int row0 = blockIdx.y * 128;
    const int col0 = blockIdx.x * 128;

    const uint32_t smA = (uint32_t)__cvta_generic_to_shared(sm);
    const uint32_t smB = smA + 32768;

    // ---- cp.async mapping: thread -> row (tid>>1), two 16B chunks (tid&1)*2+{0,1}
    const int crow = tid >> 1;
    const int cc0 = (tid & 1) * 2;
    const float* gA = A + (size_t)(row0 + crow) * lda + cc0 * 4;
    const float* gB = B + (size_t)(col0 + crow) * ldb + cc0 * 4;
    uint32_t sAo[2], sBo[2];
#pragma unroll
    for (int j = 0; j < 2; j++) {
        const int c4 = cc0 + j;
        const uint32_t off = crow * 64 + ((c4 ^ ((crow >> 1) & 3)) << 4);
        sAo[j] = off; sBo[j] = off;
    }

    // ---- ldmatrix per-lane byte offsets (stage-relative)
    const int g = lane >> 3;
    const int lrow = lane & 7;
    uint32_t aOff[2][4], bOff[2][2];
#pragma unroll
    for (int s = 0; s < 2; s++) {
#pragma unroll
        for (int mi = 0; mi < 4; mi++) {
            int row = wm + mi * 16 + (g & 1) * 8 + lrow;
            int c16 = s * 2 + (g >> 1);
            aOff[s][mi] = (uint32_t)(row * 64 + ((c16 ^ ((row >> 1) & 3)) << 4));
        }
#pragma unroll
        for (int p = 0; p < 2; p++) {
            int row = wn + p * 16 + (g & 1) * 8 + lrow;
            int c16 = s * 2 + (g >> 1);
            bOff[s][p] = (uint32_t)(row * 64 + ((c16 ^ ((row >> 1) & 3)) << 4));
        }
    }

    float acc[4][4][4];
#pragma unroll
    for (int mi = 0; mi < 4; mi++)
#pragma unroll
        for (int ni = 0; ni < 4; ni++)
#pragma unroll
            for (int q = 0; q < 4; q++) acc[mi][ni][q] = 0.f;

    const int nIter = K / 16;

#define ISSUE(it) do {                                                  \
        const int st_ = (it) & 3;                                        \
        const uint32_t aB_ = smA + st_ * 8192;                           \
        const uint32_t bB_ = smB + st_ * 8192;                           \
        const float* ga_ = gA + (it) * 16;                               \
        const float* gb_ = gB + (it) * 16;                               \
        cp16(aB_ + sAo[0], ga_);                                         \
        cp16(aB_ + sAo[1], ga_ + 4);                                     \
        cp16(bB_ + sBo[0], gb_);                                         \
        cp16(bB_ + sBo[1], gb_ + 4);                                     \
        CP_COMMIT();                                                     \
    } while (0)

    if (0 < nIter) ISSUE(0);
    if (1 < nIter) ISSUE(1);
    if (2 < nIter) ISSUE(2);

    for (int it = 0; it < nIter; ++it) {
        const int rem = nIter - 1 - it;
        if (rem >= 2)      { CP_WAIT(2); }
        else if (rem == 1) { CP_WAIT(1); }
        else               { CP_WAIT(0); }
        __syncthreads();

        if (it + 3 < nIter) ISSUE(it + 3);

        const uint32_t aBase = smA + (it & 3) * 8192;
        const uint32_t bBase = smB + (it & 3) * 8192;
#pragma unroll
        for (int s = 0; s < 2; s++) {
            unsigned a[4][4], b[2][4];
#pragma unroll
            for (int mi = 0; mi < 4; mi++) {
                asm volatile("ldmatrix.sync.aligned.m8n8.x4.shared.b16 {%0,%1,%2,%3}, [%4];"
                             : "=r"(a[mi][0]), "=r"(a[mi][1]), "=r"(a[mi][2]), "=r"(a[mi][3])
                             : "r"(aBase + aOff[s][mi]));
            }
#pragma unroll
            for (int p = 0; p < 2; p++) {
                asm volatile("ldmatrix.sync.aligned.m8n8.x4.shared.b16 {%0,%1,%2,%3}, [%4];"
                             : "=r"(b[p][0]), "=r"(b[p][1]), "=r"(b[p][2]), "=r"(b[p][3])
                             : "r"(bBase + bOff[s][p]));
            }
#pragma unroll
            for (int mi = 0; mi < 4; mi++)
#pragma unroll
                for (int ni = 0; ni < 4; ni++) {
                    unsigned bb0 = b[ni >> 1][(ni & 1)];
                    unsigned bb1 = b[ni >> 1][(ni & 1) + 2];
                    asm volatile(
                        "mma.sync.aligned.m16n8k8.row.col.f32.tf32.tf32.f32 "
                        "{%0,%1,%2,%3}, {%4,%5,%6,%7}, {%8,%9}, {%0,%1,%2,%3};"
                        : "+f"(acc[mi][ni][0]), "+f"(acc[mi][ni][1]),
                          "+f"(acc[mi][ni][2]), "+f"(acc[mi][ni][3])
                        : "r"(a[mi][0]), "r"(a[mi][1]), "r"(a[mi][2]), "r"(a[mi][3]),
                          "r"(bb0), "r"(bb1));
                }
        }
        __syncthreads();
    }
#undef ISSUE

    // ---- epilogue
#pragma unroll
    for (int mi = 0; mi < 4; mi++) {
        const int r = row0 + wm + mi * 16 + (lane >> 2);
#pragma unroll
        for (int ni = 0; ni < 4; ni++) {
            const int c = col0 + wn + ni * 8 + (lane & 3) * 2;
            float2 v0 = make_float2(acc[mi][ni][0], acc[mi][ni][1]);
            float2 v1 = make_float2(acc[mi][ni][2], acc[mi][ni][3]);
            if (bias) {
                float b0 = bias[c], b1 = bias[c + 1];
                v0.x += b0; v0.y += b1; v1.x += b0; v1.y += b1;
            }
            if (act == 1) {
                v0.x = softplusf(v0.x); v0.y = softplusf(v0.y);
                v1.x = softplusf(v1.x); v1.y = softplusf(v1.y);
            }
            *(float2*)&C[(size_t)r * N + c] = v0;
            *(float2*)&C[(size_t)(r + 8) * N + c] = v1;
        }
    }
}

// ============================================================================
// Depthwise causal conv1d (d_conv=4) + bias + SiLU.
// ============================================================================
__global__ __launch_bounds__(256) void conv_silu_kernel(
    const float* __restrict__ cw, const float* __restrict__ cb)
{
    const int idx = blockIdx.x * 256 + threadIdx.x;
    const int d = idx % D_INNER;
    const int m = idx / D_INNER;
    const int l = m & (LSEQ - 1);
    const float* base = g_xr + (size_t)m * (2 * D_INNER) + d;
    float acc = cb[d];
#pragma unroll
    for (int j = 0; j < 4; j++) {
        const int ll = l - 3 + j;
        if (ll >= 0)
            acc = fmaf(cw[d * 4 + j], base[(ptrdiff_t)(j - 3) * (2 * D_INNER)], acc);
    }
    g_h[idx] = siluf(acc);
}

// ============================================================================
// Skinny GEMM: g_xdbl[8192,80] = g_h @ W_x^T (fp32). Also writes the dt
// columns (0..47) tf32-rounded into packed g_dtin for the dt_proj TC GEMM.
// ============================================================================
__global__ __launch_bounds__(256) void gemm_xdbl_kernel(const float* __restrict__ Wx)
{
    __shared__ __align__(16) float As[16][68];
    __shared__ __align__(16) float Bs[16][80];

    const int tid = threadIdx.x;
    const int m0 = blockIdx.x * 64;
    const int tm = tid & 63;
    const int tg = tid >> 6;
    const int arow = tid >> 2;
    const int acol = (tid & 3) * 4;

    float acc[20];
#pragma unroll
    for (int j = 0; j < 20; j++) acc[j] = 0.f;

    const float* Ag = g_h + (size_t)(m0 + arow) * D_INNER + acol;

    for (int k0 = 0; k0 < D_INNER; k0 += 16) {
        float4 av = *(const float4*)(Ag + k0);
        As[acol + 0][arow] = av.x; As[acol + 1][arow] = av.y;
        As[acol + 2][arow] = av.z; As[acol + 3][arow] = av.w;
#pragma unroll
        for (int s = 0; s < 2; s++) {
            const int i = s * 256 + tid;
            if (i < 320) {
                const int nn = i >> 2;
                const int kq = (i & 3) * 4;
                float4 bv = *(const float4*)(Wx + (size_t)nn * D_INNER + k0 + kq);
                Bs[kq + 0][nn] = bv.x; Bs[kq + 1][nn] = bv.y;
                Bs[kq + 2][nn] = bv.z; Bs[kq + 3][nn] = bv.w;
            }
        }
        __syncthreads();
#pragma unroll
        for (int kk = 0; kk < 16; kk++) {
            const float a = As[kk][tm];
            float bvals[20];
            const float* brow = &Bs[kk][tg * 20];
            *(float4*)(bvals)      = *(const float4*)(brow);
            *(float4*)(bvals + 4)  = *(const float4*)(brow + 4);
            *(float4*)(bvals + 8)  = *(const float4*)(brow + 8);
            *(float4*)(bvals + 12) = *(const float4*)(brow + 12);
            *(float4*)(bvals + 16) = *(const float4*)(brow + 16);
#pragma unroll
            for (int j = 0; j < 20; j++) acc[j] = fmaf(a, bvals[j], acc[j]);
        }
        __syncthreads();
    }

    float* Cp = g_xdbl + (size_t)(m0 + tm) * XDBL_N + tg * 20;
#pragma unroll
    for (int j = 0; j < 20; j++) Cp[j] = acc[j];

    const int cbase = tg * 20;
    if (cbase < DT_RANK) {
        float* Dq = g_dtin + (size_t)(m0 + tm) * DT_RANK;
#pragma unroll
        for (int j = 0; j < 20; j++) {
            const int col = cbase + j;
            if (col < DT_RANK) Dq[col] = __uint_as_float(f2tf32(acc[j]));
        }
    }
}

// ============================================================================
// Selective scan, fused with +u*D residual and *silu(res) gating.
// Writes y tf32-rounded (feeds out_proj TC GEMM).
// ============================================================================
__global__ __launch_bounds__(256) void scan_kernel(
    const float* __restrict__ A_log, const float* __restrict__ Dp)
{
    const int lane = threadIdx.x & 31;
    const int warp = threadIdx.x >> 5;
    const int n = lane & 15;
    const int d = blockIdx.x * 16 + warp * 2 + (lane >> 4);
    const int b = blockIdx.y;

    const float Alg = -__expf(A_log[d * D_STATE + n]) * 1.4426950408889634f;
    const float Dd = Dp[d];
    float state = 0.f;

    const float* dptr = g_delta + (size_t)b * LSEQ * D_INNER + d;
    const float* uptr = g_h + (size_t)b * LSEQ * D_INNER + d;
    const float* rptr = g_xr + (size_t)b * LSEQ * (2 * D_INNER) + D_INNER + d;
    const float* xdp = g_xdbl + (size_t)b * LSEQ * XDBL_N;
    float* yptr = g_y + (size_t)b * LSEQ * D_INNER + d;

#pragma unroll 2
    for (int t = 0; t < LSEQ; t++) {
        const float dt = __ldg(dptr);
        const float ut = __ldg(uptr);
        const float Bn = __ldg(xdp + DT_RANK + n);
        const float Cn = __ldg(xdp + DT_RANK + D_STATE + n);

        const float dA = exp2f(dt * Alg);
        state = fmaf(dA, state, dt * Bn * ut);

        float p = state * Cn;
        p += __shfl_xor_sync(0xffffffffu, p, 1);
        p += __shfl_xor_sync(0xffffffffu, p, 2);
        p += __shfl_xor_sync(0xffffffffu, p, 4);
        p += __shfl_xor_sync(0xffffffffu, p, 8);

        if (n == 0) {
            const float rv = __ldg(rptr);
            *yptr = __uint_as_float(f2tf32((p + ut * Dd) * siluf(rv)));
        }
        dptr += D_INNER;
        uptr += D_INNER;
        rptr += 2 * D_INNER;
        xdp += XDBL_N;
        yptr += D_INNER;
    }
}

// ============================================================================
// kernel_launch
// Inputs: x, W_in, conv_w, conv_b, W_x, W_dt, b_dt, A_log, D, W_out
// ============================================================================
extern "C" void kernel_launch(void* const* d_in, const int* in_sizes, int n_in,
                              void* d_out, int out_size)
{
    const float* x      = (const float*)d_in[0];
    const float* W_in   = (const float*)d_in[1];
    const float* conv_w = (const float*)d_in[2];
    const float* conv_b = (const float*)d_in[3];
    const float* W_x    = (const float*)d_in[4];
    const float* W_dt   = (const float*)d_in[5];
    const float* b_dt   = (const float*)d_in[6];
    const float* A_log  = (const float*)d_in[7];
    const float* Dp     = (const float*)d_in[8];
    const float* W_out  = (const float*)d_in[9];
    float* out = (float*)d_out;

    float *xr, *delta, *y, *xt, *wint, *wdtt, *woutt, *dtin;
    cudaGetSymbolAddress((void**)&xr, g_xr);
    cudaGetSymbolAddress((void**)&delta, g_delta);
    cudaGetSymbolAddress((void**)&y, g_y);
    cudaGetSymbolAddress((void**)&xt, g_xt);
    cudaGetSymbolAddress((void**)&wint, g_wint);
    cudaGetSymbolAddress((void**)&wdtt, g_wdtt);
    cudaGetSymbolAddress((void**)&woutt, g_woutt);
    cudaGetSymbolAddress((void**)&dtin, g_dtin);

    const int SMEM_BYTES = 65536;
    static int attr_done = 0;
    if (!attr_done) {
        cudaFuncSetAttribute(tf32_gemm_ca, cudaFuncAttributeMaxDynamicSharedMemorySize,
                             SMEM_BYTES);
        attr_done = 1;
    }

    // 0) tf32-round operands into scratch
    {
        int n4;
        n4 = MROWS * D_MODEL / 4;
        cvt_tf32_kernel<<<(n4 + 255) / 256, 256>>>((const float4*)x, (float4*)xt, n4);
        n4 = 2 * D_INNER * D_MODEL / 4;
        cvt_tf32_kernel<<<(n4 + 255) / 256, 256>>>((const float4*)W_in, (float4*)wint, n4);
        n4 = D_INNER * DT_RANK / 4;
        cvt_tf32_kernel<<<(n4 + 255) / 256, 256>>>((const float4*)W_dt, (float4*)wdtt, n4);
        n4 = D_MODEL * D_INNER / 4;
        cvt_tf32_kernel<<<(n4 + 255) / 256, 256>>>((const float4*)W_out, (float4*)woutt, n4);
    }

    // 1) in_proj (TC tf32): xr[8192,3072] = xt @ wint^T
    tf32_gemm_ca<<<dim3(2 * D_INNER / 128, MROWS / 128), 256, SMEM_BYTES>>>(
        MROWS, 2 * D_INNER, D_MODEL, xt, D_MODEL, wint, D_MODEL, nullptr, xr, 0);

    // 2) depthwise causal conv + silu -> g_h
    conv_silu_kernel<<<(MROWS * D_INNER) / 256, 256>>>(conv_w, conv_b);

    // 3) x_proj (fp32): g_xdbl[8192,80] = g_h @ W_x^T ; also packs tf32 dt cols
    gemm_xdbl_kernel<<<MROWS / 64, 256>>>(W_x);

    // 4) dt_proj + softplus (TC tf32): delta = softplus(dtin @ wdtt^T + b_dt)
    tf32_gemm_ca<<<dim3(D_INNER / 128, MROWS / 128), 256, SMEM_BYTES>>>(
        MROWS, D_INNER, DT_RANK, dtin, DT_RANK, wdtt, DT_RANK, b_dt, delta, 1);

    // 5) selective scan + D-residual + gating -> g_y (tf32-rounded)
    scan_kernel<<<dim3(D_INNER / 16, NBATCH), 256>>>(A_log, Dp);

    // 6) out_proj (TC tf32): out = g_y @ woutt^T
    tf32_gemm_ca<<<dim3(D_MODEL / 128, MROWS / 128), 256, SMEM_BYTES>>>(
        MROWS, D_MODEL, D_INNER, y, D_INNER, woutt, D_INNER, nullptr, out, 0);
}

// round 5
// speedup vs baseline: 1.0615x; 1.0615x over previous
#include <cuda_runtime.h>
#include <math.h>
#include <stdint.h>

#define D_MODEL 768
#define D_INNER 1536
#define NBATCH 4
#define LSEQ 2048
#define MROWS (NBATCH * LSEQ)      // 8192
#define DT_RANK 48
#define D_STATE 16
#define XDBL_N (DT_RANK + 2 * D_STATE)   // 80

// -------- scratch (device globals; no allocation allowed) --------
__device__ __align__(16) float g_xr[(size_t)MROWS * 2 * D_INNER];   // in_proj out
__device__ __align__(16) float g_h[(size_t)MROWS * D_INNER];        // conv+silu (fp32)
__device__ __align__(16) float g_ht[(size_t)MROWS * D_INNER];       // conv+silu (tf32-rounded)
__device__ __align__(16) float g_xdbl[(size_t)MROWS * XDBL_N];      // x_proj out [8192,80]
__device__ __align__(16) float g_dtin[(size_t)MROWS * DT_RANK];     // dt cols, tf32-rounded
__device__ __align__(16) float g_delta[(size_t)MROWS * D_INNER];    // softplus(dt_proj)
__device__ __align__(16) float g_y[(size_t)MROWS * D_INNER];        // scan out (tf32-rounded)
// tf32-rounded operand copies
__device__ __align__(16) float g_xt[(size_t)MROWS * D_MODEL];
__device__ __align__(16) float g_wint[(size_t)2 * D_INNER * D_MODEL];
__device__ __align__(16) float g_wdtt[(size_t)D_INNER * DT_RANK];
__device__ __align__(16) float g_woutt[(size_t)D_MODEL * D_INNER];
__device__ __align__(16) float g_wxt[(size_t)XDBL_N * D_INNER];

__device__ __forceinline__ float siluf(float v) { return v / (1.f + __expf(-v)); }
__device__ __forceinline__ float softplusf(float v) {
    return v > 20.f ? v : log1pf(__expf(v));
}
__device__ __forceinline__ unsigned f2tf32(float f) {
    unsigned u;
    asm("cvt.rna.tf32.f32 %0, %1;" : "=r"(u) : "f"(f));
    return u;
}
#define CP_COMMIT() asm volatile("cp.async.commit_group;" ::: "memory")
#define CP_WAIT1()  asm volatile("cp.async.wait_group 1;" ::: "memory")

__device__ __forceinline__ void cp16z(uint32_t s, const void* g, unsigned sz) {
    asm volatile("cp.async.cg.shared.global [%0], [%1], 16, %2;"
                 :: "r"(s), "l"(g), "r"(sz));
}

// ============================================================================
// Elementwise fp32 -> tf32(rna)-rounded copy (vectorized).
// ============================================================================
__global__ __launch_bounds__(256) void cvt_tf32_kernel(
    const float4* __restrict__ src, float4* __restrict__ dst, int n4)
{
    int i = blockIdx.x * 256 + threadIdx.x;
    if (i < n4) {
        float4 v = src[i];
        v.x = __uint_as_float(f2tf32(v.x));
        v.y = __uint_as_float(f2tf32(v.y));
        v.z = __uint_as_float(f2tf32(v.z));
        v.w = __uint_as_float(f2tf32(v.w));
        dst[i] = v;
    }
}

// ============================================================================
// TF32 tensor-core NT GEMM, 3-stage cp.async, register-double-buffered.
// C[M,N] = A[M,K]*B[N,K]^T (+bias, +softplus). A,B pre-rounded to tf32 bits.
// Req: M%128==0, K%4==0, lda/ldb%4==0. N arbitrary (zfill + store guards).
// Block 128x128, BK=32, 256 thr, 8 warps 2(M)x4(N), warp tile 64x32.
// smem stage = 32KB (A 16K + B 16K), 3 stages = 96KB. Swizzle: chunk ^= row&7.
// Optional C2: packed tf32-rounded copy of cols < DT_RANK (ld = DT_RANK).
// ============================================================================
__global__ __launch_bounds__(256) void tf32_gemm_v2(
    int M, int N, int K,
    const float* __restrict__ A, int lda,
    const float* __restrict__ B, int ldb,
    const float* __restrict__ bias,
    float* __restrict__ C, int act, float* __restrict__ C2)
{
    extern __shared__ __align__(16) char sm[];

    const int tid = threadIdx.x;
    const int lane = tid & 31;
    const int warp = tid >> 5;
    const int wm = (warp & 1) * 64;
    const int wn = (warp >> 1) * 32;
    const int row0 = blockIdx.y * 128;
    const int col0 = blockIdx.x * 128;
    const uint32_t smBase = (uint32_t)__cvta_generic_to_shared(sm);

    // ---- cp.async mapping: thread -> row (tid>>1), 4 chunks at (tid&1)*4 + j
    const int crow = tid >> 1;
    const int cb4 = (tid & 1) * 4;
    const float* gA = A + (size_t)(row0 + crow) * lda;
    const int browg = col0 + crow;
    const bool brval = browg < N;
    const float* gB = B + (size_t)(brval ? browg : 0) * ldb;
    uint32_t so[4];
#pragma unroll
    for (int j = 0; j < 4; j++)
        so[j] = (uint32_t)(crow * 128 + (((cb4 + j) ^ (crow & 7)) << 4));

    // ---- ldmatrix per-lane offsets (stage-relative)
    const int g = lane >> 3;
    const int lrow = lane & 7;
    uint32_t aOff[4][4], bOff[4][2];
#pragma unroll
    for (int s = 0; s < 4; s++) {
        const int c16 = s * 2 + (g >> 1);
#pragma unroll
        for (int mi = 0; mi < 4; mi++) {
            int row = wm + mi * 16 + (g & 1) * 8 + lrow;
            aOff[s][mi] = (uint32_t)(row * 128 + ((c16 ^ (row & 7)) << 4));
        }
#pragma unroll
        for (int p = 0; p < 2; p++) {
            int row = wn + p * 16 + (g & 1) * 8 + lrow;
            bOff[s][p] = (uint32_t)(row * 128 + ((c16 ^ (row & 7)) << 4));
        }
    }

    float acc[4][4][4];
#pragma unroll
    for (int mi = 0; mi < 4; mi++)
#pragma unroll
        for (int ni = 0; ni < 4; ni++)
#pragma unroll
            for (int q = 0; q < 4; q++) acc[mi][ni][q] = 0.f;

    const int nIter = (K + 31) / 32;

#define ISSUE(it, st) do {                                                   \
        const uint32_t ab_ = smBase + (uint32_t)(st) * 32768u;                \
        const uint32_t bb_ = ab_ + 16384u;                                    \
        const int k0_ = (it) * 32;                                            \
        _Pragma("unroll")                                                     \
        for (int j = 0; j < 4; j++) {                                         \
            const int kc = k0_ + (cb4 + j) * 4;                               \
            const bool kv = kc < K;                                           \
            const int kcl = kv ? kc : 0;                                      \
            cp16z(ab_ + so[j], gA + kcl, kv ? 16u : 0u);                      \
            cp16z(bb_ + so[j], gB + kcl, (kv && brval) ? 16u : 0u);           \
        }                                                                     \
        CP_COMMIT();                                                          \
    } while (0)

#define LDFRAGS(sl, AF, BF, ab_, bb_) do {                                    \
        _Pragma("unroll")                                                     \
        for (int mi = 0; mi < 4; mi++)                                        \
            asm volatile("ldmatrix.sync.aligned.m8n8.x4.shared.b16 "          \
                         "{%0,%1,%2,%3}, [%4];"                               \
                         : "=r"(AF[mi][0]), "=r"(AF[mi][1]),                  \
                           "=r"(AF[mi][2]), "=r"(AF[mi][3])                   \
                         : "r"((ab_) + aOff[sl][mi]));                        \
        _Pragma("unroll")                                                     \
        for (int p = 0; p < 2; p++)                                           \
            asm volatile("ldmatrix.sync.aligned.m8n8.x4.shared.b16 "          \
                         "{%0,%1,%2,%3}, [%4];"                               \
                         : "=r"(BF[p][0]), "=r"(BF[p][1]),                    \
                           "=r"(BF[p][2]), "=r"(BF[p][3])                     \
                         : "r"((bb_) + bOff[sl][p]));                         \
    } while (0)

#define DO_MMA(AF, BF) do {                                                   \
        _Pragma("unroll")                                                     \
        for (int mi = 0; mi < 4; mi++)                                        \
            _Pragma("unroll")                                                 \
            for (int ni = 0; ni < 4; ni++) {                                  \
                unsigned bb0 = BF[ni >> 1][(ni & 1)];                         \
                unsigned bb1 = BF[ni >> 1][(ni & 1) + 2];                     \
                asm volatile(                                                 \
                    "mma.sync.aligned.m16n8k8.row.col.f32.tf32.tf32.f32 "     \
                    "{%0,%1,%2,%3}, {%4,%5,%6,%7}, {%8,%9}, {%0,%1,%2,%3};"   \
                    : "+f"(acc[mi][ni][0]), "+f"(acc[mi][ni][1]),             \
                      "+f"(acc[mi][ni][2]), "+f"(acc[mi][ni][3])              \
                    : "r"(AF[mi][0]), "r"(AF[mi][1]),                         \
                      "r"(AF[mi][2]), "r"(AF[mi][3]),                         \
                      "r"(bb0), "r"(bb1));                                    \
            }                                                                 \
    } while (0)

    ISSUE(0, 0);
    if (nIter > 1) ISSUE(1, 1);
    else CP_COMMIT();
    CP_WAIT1();
    __syncthreads();

    int cs = 0, is_ = 2;
    for (int it = 0; it < nIter; ++it) {
        if (it + 2 < nIter) ISSUE(it + 2, is_);
        else CP_COMMIT();  // empty group keeps wait_group(1) invariant

        const uint32_t ab = smBase + (uint32_t)cs * 32768u;
        const uint32_t bb = ab + 16384u;
        unsigned afr[2][4][4], bfr[2][2][4];
        LDFRAGS(0, afr[0], bfr[0], ab, bb);
#pragma unroll
        for (int s = 0; s < 4; s++) {
            const int cur = s & 1, nxt = cur ^ 1;
            if (s < 3) {
                switch (s + 1) {
                case 1: LDFRAGS(1, afr[nxt], bfr[nxt], ab, bb); break;
                case 2: LDFRAGS(2, afr[nxt], bfr[nxt], ab, bb); break;
                default: LDFRAGS(3, afr[nxt], bfr[nxt], ab, bb); break;
                }
            }
            DO_MMA(afr[cur], bfr[cur]);
        }

        CP_WAIT1();
        __syncthreads();
        cs = (cs == 2) ? 0 : cs + 1;
        is_ = (is_ == 2) ? 0 : is_ + 1;
    }
#undef ISSUE
#undef LDFRAGS
#undef DO_MMA

    // ---- epilogue
#pragma unroll
    for (int mi = 0; mi < 4; mi++) {
        const int r = row0 + wm + mi * 16 + (lane >> 2);
#pragma unroll
        for (int ni = 0; ni < 4; ni++) {
            const int c = col0 + wn + ni * 8 + (lane & 3) * 2;
            if (c < N) {
                float2 v0 = make_float2(acc[mi][ni][0], acc[mi][ni][1]);
                float2 v1 = make_float2(acc[mi][ni][2], acc[mi][ni][3]);
                if (bias) {
                    float b0 = bias[c], b1 = bias[c + 1];
                    v0.x += b0; v0.y += b1; v1.x += b0; v1.y += b1;
                }
                if (act == 1) {
                    v0.x = softplusf(v0.x); v0.y = softplusf(v0.y);
                    v1.x = softplusf(v1.x); v1.y = softplusf(v1.y);
                }
                *(float2*)&C[(size_t)r * N + c] = v0;
                *(float2*)&C[(size_t)(r + 8) * N + c] = v1;
                if (C2 && c < DT_RANK) {
                    float* d0 = C2 + (size_t)r * DT_RANK + c;
                    float* d1 = C2 + (size_t)(r + 8) * DT_RANK + c;
                    d0[0] = __uint_as_float(f2tf32(v0.x));
                    d0[1] = __uint_as_float(f2tf32(v0.y));
                    d1[0] = __uint_as_float(f2tf32(v1.x));
                    d1[1] = __uint_as_float(f2tf32(v1.y));
                }
            }
        }
    }
}

// ============================================================================
// Depthwise causal conv1d (d_conv=4) + bias + SiLU; writes fp32 + tf32 copies.
// ============================================================================
__global__ __launch_bounds__(256) void conv_silu_kernel(
    const float* __restrict__ cw, const float* __restrict__ cb)
{
    const int idx = blockIdx.x * 256 + threadIdx.x;
    const int d = idx % D_INNER;
    const int m = idx / D_INNER;
    const int l = m & (LSEQ - 1);
    const float* base = g_xr + (size_t)m * (2 * D_INNER) + d;
    float acc = cb[d];
#pragma unroll
    for (int j = 0; j < 4; j++) {
        const int ll = l - 3 + j;
        if (ll >= 0)
            acc = fmaf(cw[d * 4 + j], base[(ptrdiff_t)(j - 3) * (2 * D_INNER)], acc);
    }
    const float hv = siluf(acc);
    g_h[idx] = hv;
    g_ht[idx] = __uint_as_float(f2tf32(hv));
}

// ============================================================================
// Selective scan, fused with +u*D residual and *silu(res) gating.
// Writes y tf32-rounded (feeds out_proj TC GEMM).
// ============================================================================
__global__ __launch_bounds__(256) void scan_kernel(
    const float* __restrict__ A_log, const float* __restrict__ Dp)
{
    const int lane = threadIdx.x & 31;
    const int warp = threadIdx.x >> 5;
    const int n = lane & 15;
    const int d = blockIdx.x * 16 + warp * 2 + (lane >> 4);
    const int b = blockIdx.y;

    const float Alg = -__expf(A_log[d * D_STATE + n]) * 1.4426950408889634f;
    const float Dd = Dp[d];
    float state = 0.f;

    const float* dptr = g_delta + (size_t)b * LSEQ * D_INNER + d;
    const float* uptr = g_h + (size_t)b * LSEQ * D_INNER + d;
    const float* rptr = g_xr + (size_t)b * LSEQ * (2 * D_INNER) + D_INNER + d;
    const float* xdp = g_xdbl + (size_t)b * LSEQ * XDBL_N;
    float* yptr = g_y + (size_t)b * LSEQ * D_INNER + d;

#pragma unroll 2
    for (int t = 0; t < LSEQ; t++) {
        const float dt = __ldg(dptr);
        const float ut = __ldg(uptr);
        const float Bn = __ldg(xdp + DT_RANK + n);
        const float Cn = __ldg(xdp + DT_RANK + D_STATE + n);

        const float dA = exp2f(dt * Alg);
        state = fmaf(dA, state, dt * Bn * ut);

        float p = state * Cn;
        p += __shfl_xor_sync(0xffffffffu, p, 1);
        p += __shfl_xor_sync(0xffffffffu, p, 2);
        p += __shfl_xor_sync(0xffffffffu, p, 4);
        p += __shfl_xor_sync(0xffffffffu, p, 8);

        if (n == 0) {
            const float rv = __ldg(rptr);
            *yptr = __uint_as_float(f2tf32((p + ut * Dd) * siluf(rv)));
        }
        dptr += D_INNER;
        uptr += D_INNER;
        rptr += 2 * D_INNER;
        xdp += XDBL_N;
        yptr += D_INNER;
    }
}

// ============================================================================
// kernel_launch
// Inputs: x, W_in, conv_w, conv_b, W_x, W_dt, b_dt, A_log, D, W_out
// ============================================================================
extern "C" void kernel_launch(void* const* d_in, const int* in_sizes, int n_in,
                              void* d_out, int out_size)
{
    const float* x      = (const float*)d_in[0];
    const float* W_in   = (const float*)d_in[1];
    const float* conv_w = (const float*)d_in[2];
    const float* conv_b = (const float*)d_in[3];
    const float* W_x    = (const float*)d_in[4];
    const float* W_dt   = (const float*)d_in[5];
    const float* b_dt   = (const float*)d_in[6];
    const float* A_log  = (const float*)d_in[7];
    const float* Dp     = (const float*)d_in[8];
    const float* W_out  = (const float*)d_in[9];
    float* out = (float*)d_out;

    float *xr, *delta, *y, *xt, *wint, *wdtt, *woutt, *wxt, *dtin, *xdbl, *ht;
    cudaGetSymbolAddress((void**)&xr, g_xr);
    cudaGetSymbolAddress((void**)&delta, g_delta);
    cudaGetSymbolAddress((void**)&y, g_y);
    cudaGetSymbolAddress((void**)&xt, g_xt);
    cudaGetSymbolAddress((void**)&wint, g_wint);
    cudaGetSymbolAddress((void**)&wdtt, g_wdtt);
    cudaGetSymbolAddress((void**)&woutt, g_woutt);
    cudaGetSymbolAddress((void**)&wxt, g_wxt);
    cudaGetSymbolAddress((void**)&dtin, g_dtin);
    cudaGetSymbolAddress((void**)&xdbl, g_xdbl);
    cudaGetSymbolAddress((void**)&ht, g_ht);

    const int SMEM_BYTES = 98304;
    cudaFuncSetAttribute(tf32_gemm_v2, cudaFuncAttributeMaxDynamicSharedMemorySize,
                         SMEM_BYTES);

    // 0) tf32-round operands into scratch
    {
        int n4;
        n4 = MROWS * D_MODEL / 4;
        cvt_tf32_kernel<<<(n4 + 255) / 256, 256>>>((const float4*)x, (float4*)xt, n4);
        n4 = 2 * D_INNER * D_MODEL / 4;
        cvt_tf32_kernel<<<(n4 + 255) / 256, 256>>>((const float4*)W_in, (float4*)wint, n4);
        n4 = D_INNER * DT_RANK / 4;
        cvt_tf32_kernel<<<(n4 + 255) / 256, 256>>>((const float4*)W_dt, (float4*)wdtt, n4);
        n4 = D_MODEL * D_INNER / 4;
        cvt_tf32_kernel<<<(n4 + 255) / 256, 256>>>((const float4*)W_out, (float4*)woutt, n4);
        n4 = XDBL_N * D_INNER / 4;
        cvt_tf32_kernel<<<(n4 + 255) / 256, 256>>>((const float4*)W_x, (float4*)wxt, n4);
    }

    // 1) in_proj (TC tf32): xr[8192,3072] = xt @ wint^T
    tf32_gemm_v2<<<dim3(2 * D_INNER / 128, MROWS / 128), 256, SMEM_BYTES>>>(
        MROWS, 2 * D_INNER, D_MODEL, xt, D_MODEL, wint, D_MODEL, nullptr, xr, 0, nullptr);

    // 2) depthwise causal conv + silu -> g_h (fp32) + g_ht (tf32)
    conv_silu_kernel<<<(MROWS * D_INNER) / 256, 256>>>(conv_w, conv_b);

    // 3) x_proj (TC tf32, N=80 in one padded tile): xdbl = ht @ wxt^T;
    //    epilogue also packs tf32-rounded dt cols into g_dtin.
    tf32_gemm_v2<<<dim3(1, MROWS / 128), 256, SMEM_BYTES>>>(
        MROWS, XDBL_N, D_INNER, ht, D_INNER, wxt, D_INNER, nullptr, xdbl, 0, dtin);

    // 4) dt_proj + softplus (TC tf32): delta = softplus(dtin @ wdtt^T + b_dt)
    tf32_gemm_v2<<<dim3(D_INNER / 128, MROWS / 128), 256, SMEM_BYTES>>>(
        MROWS, D_INNER, DT_RANK, dtin, DT_RANK, wdtt, DT_RANK, b_dt, delta, 1, nullptr);

    // 5) selective scan + D-residual + gating -> g_y (tf32-rounded)
    scan_kernel<<<dim3(D_INNER / 16, NBATCH), 256>>>(A_log, Dp);

    // 6) out_proj (TC tf32): out = g_y @ woutt^T
    tf32_gemm_v2<<<dim3(D_MODEL / 128, MROWS / 128), 256, SMEM_BYTES>>>(
        MROWS, D_MODEL, D_INNER, y, D_INNER, woutt, D_INNER, nullptr, out, 0, nullptr);
}

// round 7
// speedup vs baseline: 1.9675x; 1.8536x over previous
#include <cuda_runtime.h>
#include <math.h>
#include <stdint.h>

#define D_MODEL 768
#define D_INNER 1536
#define NBATCH 4
#define LSEQ 2048
#define MROWS (NBATCH * LSEQ)      // 8192
#define DT_RANK 48
#define D_STATE 16
#define XDBL_N (DT_RANK + 2 * D_STATE)   // 80
#define NC 32                       // scan chunks
#define CL (LSEQ / NC)              // 64 steps per chunk
#define PLANE (NBATCH * D_INNER * D_STATE)   // 98304

// -------- scratch (device globals; no allocation allowed) --------
__device__ __align__(16) float g_xr[(size_t)MROWS * 2 * D_INNER];   // in_proj out
__device__ __align__(16) float g_h[(size_t)MROWS * D_INNER];        // conv+silu (fp32)
__device__ __align__(16) float g_ht[(size_t)MROWS * D_INNER];       // conv+silu (tf32)
__device__ __align__(16) float g_xdbl[(size_t)MROWS * XDBL_N];      // x_proj out
__device__ __align__(16) float g_dtin[(size_t)MROWS * DT_RANK];     // dt cols (tf32)
__device__ __align__(16) float g_delta[(size_t)MROWS * D_INNER];    // softplus(dt_proj)
__device__ __align__(16) float g_y[(size_t)MROWS * D_INNER];        // scan out (tf32)
// scan chunk summaries / incoming states, layout [c][b*D_INNER*16 + d*16 + n]
__device__ __align__(16) float g_ca[(size_t)NC * PLANE];
__device__ __align__(16) float g_cs[(size_t)NC * PLANE];
__device__ __align__(16) float g_hin[(size_t)NC * PLANE];
// tf32-rounded operand copies
__device__ __align__(16) float g_xt[(size_t)MROWS * D_MODEL];
__device__ __align__(16) float g_wint[(size_t)2 * D_INNER * D_MODEL];
__device__ __align__(16) float g_wdtt[(size_t)D_INNER * DT_RANK];
__device__ __align__(16) float g_woutt[(size_t)D_MODEL * D_INNER];
__device__ __align__(16) float g_wxt[(size_t)XDBL_N * D_INNER];

__device__ __forceinline__ float siluf(float v) { return v / (1.f + __expf(-v)); }
__device__ __forceinline__ float softplusf(float v) {
    return v > 20.f ? v : log1pf(__expf(v));
}
__device__ __forceinline__ unsigned f2tf32(float f) {
    unsigned u;
    asm("cvt.rna.tf32.f32 %0, %1;" : "=r"(u) : "f"(f));
    return u;
}
#define CP_COMMIT() asm volatile("cp.async.commit_group;" ::: "memory")
#define CP_WAIT1()  asm volatile("cp.async.wait_group 1;" ::: "memory")

__device__ __forceinline__ void cp16z(uint32_t s, const void* g, unsigned sz) {
    asm volatile("cp.async.cg.shared.global [%0], [%1], 16, %2;"
                 :: "r"(s), "l"(g), "r"(sz));
}

// ============================================================================
// Elementwise fp32 -> tf32(rna)-rounded copy (vectorized).
// ============================================================================
__global__ __launch_bounds__(256) void cvt_tf32_kernel(
    const float4* __restrict__ src, float4* __restrict__ dst, int n4)
{
    int i = blockIdx.x * 256 + threadIdx.x;
    if (i < n4) {
        float4 v = src[i];
        v.x = __uint_as_float(f2tf32(v.x));
        v.y = __uint_as_float(f2tf32(v.y));
        v.z = __uint_as_float(f2tf32(v.z));
        v.w = __uint_as_float(f2tf32(v.w));
        dst[i] = v;
    }
}

// ============================================================================
// TF32 tensor-core NT GEMM, 3-stage cp.async, register-double-buffered.
// (unchanged from R5; see comments there)
// ============================================================================
__global__ __launch_bounds__(256) void tf32_gemm_v2(
    int M, int N, int K,
    const float* __restrict__ A, int lda,
    const float* __restrict__ B, int ldb,
    const float* __restrict__ bias,
    float* __restrict__ C, int act, float* __restrict__ C2)
{
    extern __shared__ __align__(16) char sm[];

    const int tid = threadIdx.x;
    const int lane = tid & 31;
    const int warp = tid >> 5;
    const int wm = (warp & 1) * 64;
    const int wn = (warp >> 1) * 32;
    const int row0 = blockIdx.y * 128;
    const int col0 = blockIdx.x * 128;
    const uint32_t smBase = (uint32_t)__cvta_generic_to_shared(sm);

    const int crow = tid >> 1;
    const int cb4 = (tid & 1) * 4;
    const float* gA = A + (size_t)(row0 + crow) * lda;
    const int browg = col0 + crow;
    const bool brval = browg < N;
    const float* gB = B + (size_t)(brval ? browg : 0) * ldb;
    uint32_t so[4];
#pragma unroll
    for (int j = 0; j < 4; j++)
        so[j] = (uint32_t)(crow * 128 + (((cb4 + j) ^ (crow & 7)) << 4));

    const int g = lane >> 3;
    const int lrow = lane & 7;
    uint32_t aOff[4][4], bOff[4][2];
#pragma unroll
    for (int s = 0; s < 4; s++) {
        const int c16 = s * 2 + (g >> 1);
#pragma unroll
        for (int mi = 0; mi < 4; mi++) {
            int row = wm + mi * 16 + (g & 1) * 8 + lrow;
            aOff[s][mi] = (uint32_t)(row * 128 + ((c16 ^ (row & 7)) << 4));
        }
#pragma unroll
        for (int p = 0; p < 2; p++) {
            int row = wn + p * 16 + (g & 1) * 8 + lrow;
            bOff[s][p] = (uint32_t)(row * 128 + ((c16 ^ (row & 7)) << 4));
        }
    }

    float acc[4][4][4];
#pragma unroll
    for (int mi = 0; mi < 4; mi++)
#pragma unroll
        for (int ni = 0; ni < 4; ni++)
#pragma unroll
            for (int q = 0; q < 4; q++) acc[mi][ni][q] = 0.f;

    const int nIter = (K + 31) / 32;

#define ISSUE(it, st) do {                                                   \
        const uint32_t ab_ = smBase + (uint32_t)(st) * 32768u;                \
        const uint32_t bb_ = ab_ + 16384u;                                    \
        const int k0_ = (it) * 32;                                            \
        _Pragma("unroll")                                                     \
        for (int j = 0; j < 4; j++) {                                         \
            const int kc = k0_ + (cb4 + j) * 4;                               \
            const bool kv = kc < K;                                           \
            const int kcl = kv ? kc : 0;                                      \
            cp16z(ab_ + so[j], gA + kcl, kv ? 16u : 0u);                      \
            cp16z(bb_ + so[j], gB + kcl, (kv && brval) ? 16u : 0u);           \
        }                                                                     \
        CP_COMMIT();                                                          \
    } while (0)

#define LDFRAGS(sl, AF, BF, ab_, bb_) do {                                    \
        _Pragma("unroll")                                                     \
        for (int mi = 0; mi < 4; mi++)                                        \
            asm volatile("ldmatrix.sync.aligned.m8n8.x4.shared.b16 "          \
                         "{%0,%1,%2,%3}, [%4];"                               \
                         : "=r"(AF[mi][0]), "=r"(AF[mi][1]),                  \
                           "=r"(AF[mi][2]), "=r"(AF[mi][3])                   \
                         : "r"((ab_) + aOff[sl][mi]));                        \
        _Pragma("unroll")                                                     \
        for (int p = 0; p < 2; p++)                                           \
            asm volatile("ldmatrix.sync.aligned.m8n8.x4.shared.b16 "          \
                         "{%0,%1,%2,%3}, [%4];"                               \
                         : "=r"(BF[p][0]), "=r"(BF[p][1]),                    \
                           "=r"(BF[p][2]), "=r"(BF[p][3])                     \
                         : "r"((bb_) + bOff[sl][p]));                         \
    } while (0)

#define DO_MMA(AF, BF) do {                                                   \
        _Pragma("unroll")                                                     \
        for (int mi = 0; mi < 4; mi++)                                        \
            _Pragma("unroll")                                                 \
            for (int ni = 0; ni < 4; ni++) {                                  \
                unsigned bb0 = BF[ni >> 1][(ni & 1)];                         \
                unsigned bb1 = BF[ni >> 1][(ni & 1) + 2];                     \
                asm volatile(                                                 \
                    "mma.sync.aligned.m16n8k8.row.col.f32.tf32.tf32.f32 "     \
                    "{%0,%1,%2,%3}, {%4,%5,%6,%7}, {%8,%9}, {%0,%1,%2,%3};"   \
                    : "+f"(acc[mi][ni][0]), "+f"(acc[mi][ni][1]),             \
                      "+f"(acc[mi][ni][2]), "+f"(acc[mi][ni][3])              \
                    : "r"(AF[mi][0]), "r"(AF[mi][1]),                         \
                      "r"(AF[mi][2]), "r"(AF[mi][3]),                         \
                      "r"(bb0), "r"(bb1));                                    \
            }                                                                 \
    } while (0)

    ISSUE(0, 0);
    if (nIter > 1) ISSUE(1, 1);
    else CP_COMMIT();
    CP_WAIT1();
    __syncthreads();

    int cs = 0, is_ = 2;
    for (int it = 0; it < nIter; ++it) {
        if (it + 2 < nIter) ISSUE(it + 2, is_);
        else CP_COMMIT();

        const uint32_t ab = smBase + (uint32_t)cs * 32768u;
        const uint32_t bb = ab + 16384u;
        unsigned afr[2][4][4], bfr[2][2][4];
        LDFRAGS(0, afr[0], bfr[0], ab, bb);
#pragma unroll
        for (int s = 0; s < 4; s++) {
            const int cur = s & 1, nxt = cur ^ 1;
            if (s < 3) {
                switch (s + 1) {
                case 1: LDFRAGS(1, afr[nxt], bfr[nxt], ab, bb); break;
                case 2: LDFRAGS(2, afr[nxt], bfr[nxt], ab, bb); break;
                default: LDFRAGS(3, afr[nxt], bfr[nxt], ab, bb); break;
                }
            }
            DO_MMA(afr[cur], bfr[cur]);
        }

        CP_WAIT1();
        __syncthreads();
        cs = (cs == 2) ? 0 : cs + 1;
        is_ = (is_ == 2) ? 0 : is_ + 1;
    }
#undef ISSUE
#undef LDFRAGS
#undef DO_MMA

#pragma unroll
    for (int mi = 0; mi < 4; mi++) {
        const int r = row0 + wm + mi * 16 + (lane >> 2);
#pragma unroll
        for (int ni = 0; ni < 4; ni++) {
            const int c = col0 + wn + ni * 8 + (lane & 3) * 2;
            if (c < N) {
                float2 v0 = make_float2(acc[mi][ni][0], acc[mi][ni][1]);
                float2 v1 = make_float2(acc[mi][ni][2], acc[mi][ni][3]);
                if (bias) {
                    float b0 = bias[c], b1 = bias[c + 1];
                    v0.x += b0; v0.y += b1; v1.x += b0; v1.y += b1;
                }
                if (act == 1) {
                    v0.x = softplusf(v0.x); v0.y = softplusf(v0.y);
                    v1.x = softplusf(v1.x); v1.y = softplusf(v1.y);
                }
                *(float2*)&C[(size_t)r * N + c] = v0;
                *(float2*)&C[(size_t)(r + 8) * N + c] = v1;
                if (C2 && c < DT_RANK) {
                    float* d0 = C2 + (size_t)r * DT_RANK + c;
                    float* d1 = C2 + (size_t)(r + 8) * DT_RANK + c;
                    d0[0] = __uint_as_float(f2tf32(v0.x));
                    d0[1] = __uint_as_float(f2tf32(v0.y));
                    d1[0] = __uint_as_float(f2tf32(v1.x));
                    d1[1] = __uint_as_float(f2tf32(v1.y));
                }
            }
        }
    }
}

// ============================================================================
// Depthwise causal conv1d (d_conv=4) + bias + SiLU; fp32 + tf32 copies.
// ============================================================================
__global__ __launch_bounds__(256) void conv_silu_kernel(
    const float* __restrict__ cw, const float* __restrict__ cb)
{
    const int idx = blockIdx.x * 256 + threadIdx.x;
    const int d = idx % D_INNER;
    const int m = idx / D_INNER;
    const int l = m & (LSEQ - 1);
    const float* base = g_xr + (size_t)m * (2 * D_INNER) + d;
    float acc = cb[d];
#pragma unroll
    for (int j = 0; j < 4; j++) {
        const int ll = l - 3 + j;
        if (ll >= 0)
            acc = fmaf(cw[d * 4 + j], base[(ptrdiff_t)(j - 3) * (2 * D_INNER)], acc);
    }
    const float hv = siluf(acc);
    g_h[idx] = hv;
    g_ht[idx] = __uint_as_float(f2tf32(hv));
}

// ============================================================================
// Chunked parallel selective scan.
// Thread = (b, d, n, chunk); warp = 2 channels x 16 states; block = 16 channels.
// Grid (D_INNER/16, NBATCH, NC).
// Phase 1: local scan from 0 over CL steps; emit (a_chunk, s_chunk) into
//          [c][b,d,n] planes (a_chunk = exp2(Alg * sum dt)).
// ============================================================================
__global__ __launch_bounds__(256) void scan_phase1(const float* __restrict__ A_log)
{
    const int lane = threadIdx.x & 31;
    const int warp = threadIdx.x >> 5;
    const int n = lane & 15;
    const int d = blockIdx.x * 16 + warp * 2 + (lane >> 4);
    const int b = blockIdx.y;
    const int c = blockIdx.z;
    const int t0 = c * CL;

    const float Alg = -__expf(A_log[d * D_STATE + n]) * 1.4426950408889634f;
    float state = 0.f, dtsum = 0.f;

    const float* dptr = g_delta + ((size_t)b * LSEQ + t0) * D_INNER + d;
    const float* uptr = g_h + ((size_t)b * LSEQ + t0) * D_INNER + d;
    const float* xdp = g_xdbl + ((size_t)b * LSEQ + t0) * XDBL_N;

#pragma unroll 4
    for (int t = 0; t < CL; t++) {
        const float dt = __ldg(dptr);
        const float ut = __ldg(uptr);
        const float Bn = __ldg(xdp + DT_RANK + n);
        dtsum += dt;
        state = fmaf(exp2f(dt * Alg), state, dt * Bn * ut);
        dptr += D_INNER;
        uptr += D_INNER;
        xdp += XDBL_N;
    }

    const size_t idx = (size_t)c * PLANE + (((size_t)b * D_INNER + d) << 4) + n;
    g_ca[idx] = exp2f(Alg * dtsum);
    g_cs[idx] = state;
}

// ============================================================================
// Phase 2: exclusive scan over chunk summaries. Thread = (b,d,n).
// ============================================================================
__global__ __launch_bounds__(256) void scan_phase2()
{
    const size_t i = (size_t)blockIdx.x * 256 + threadIdx.x;
    float h = 0.f;
#pragma unroll
    for (int c = 0; c < NC; c++) {
        const size_t o = (size_t)c * PLANE + i;
        g_hin[o] = h;
        h = fmaf(g_ca[o], h, g_cs[o]);
    }
}

// ============================================================================
// Phase 3: re-run each chunk from its correct incoming state, fused with
// C-reduction, +u*D residual, *silu(res) gating; writes y tf32-rounded.
// ============================================================================
__global__ __launch_bounds__(256) void scan_phase3(
    const float* __restrict__ A_log, const float* __restrict__ Dp)
{
    const int lane = threadIdx.x & 31;
    const int warp = threadIdx.x >> 5;
    const int n = lane & 15;
    const int d = blockIdx.x * 16 + warp * 2 + (lane >> 4);
    const int b = blockIdx.y;
    const int c = blockIdx.z;
    const int t0 = c * CL;

    const float Alg = -__expf(A_log[d * D_STATE + n]) * 1.4426950408889634f;
    const float Dd = Dp[d];

    const size_t idx = (size_t)c * PLANE + (((size_t)b * D_INNER + d) << 4) + n;
    float state = g_hin[idx];

    const float* dptr = g_delta + ((size_t)b * LSEQ + t0) * D_INNER + d;
    const float* uptr = g_h + ((size_t)b * LSEQ + t0) * D_INNER + d;
    const float* rptr = g_xr + ((size_t)b * LSEQ + t0) * (2 * D_INNER) + D_INNER + d;
    const float* xdp = g_xdbl + ((size_t)b * LSEQ + t0) * XDBL_N;
    float* yptr = g_y + ((size_t)b * LSEQ + t0) * D_INNER + d;

#pragma unroll 4
    for (int t = 0; t < CL; t++) {
        const float dt = __ldg(dptr);
        const float ut = __ldg(uptr);
        const float Bn = __ldg(xdp + DT_RANK + n);
        const float Cn = __ldg(xdp + DT_RANK + D_STATE + n);

        state = fmaf(exp2f(dt * Alg), state, dt * Bn * ut);

        float p = state * Cn;
        p += __shfl_xor_sync(0xffffffffu, p, 1);
        p += __shfl_xor_sync(0xffffffffu, p, 2);
        p += __shfl_xor_sync(0xffffffffu, p, 4);
        p += __shfl_xor_sync(0xffffffffu, p, 8);

        if (n == 0) {
            const float rv = __ldg(rptr);
            *yptr = __uint_as_float(f2tf32((p + ut * Dd) * siluf(rv)));
        }
        dptr += D_INNER;
        uptr += D_INNER;
        rptr += 2 * D_INNER;
        xdp += XDBL_N;
        yptr += D_INNER;
    }
}

// ============================================================================
// kernel_launch
// Inputs: x, W_in, conv_w, conv_b, W_x, W_dt, b_dt, A_log, D, W_out
// ============================================================================
extern "C" void kernel_launch(void* const* d_in, const int* in_sizes, int n_in,
                              void* d_out, int out_size)
{
    const float* x      = (const float*)d_in[0];
    const float* W_in   = (const float*)d_in[1];
    const float* conv_w = (const float*)d_in[2];
    const float* conv_b = (const float*)d_in[3];
    const float* W_x    = (const float*)d_in[4];
    const float* W_dt   = (const float*)d_in[5];
    const float* b_dt   = (const float*)d_in[6];
    const float* A_log  = (const float*)d_in[7];
    const float* Dp     = (const float*)d_in[8];
    const float* W_out  = (const float*)d_in[9];
    float* out = (float*)d_out;

    float *xr, *delta, *y, *xt, *wint, *wdtt, *woutt, *wxt, *dtin, *xdbl, *ht;
    cudaGetSymbolAddress((void**)&xr, g_xr);
    cudaGetSymbolAddress((void**)&delta, g_delta);
    cudaGetSymbolAddress((void**)&y, g_y);
    cudaGetSymbolAddress((void**)&xt, g_xt);
    cudaGetSymbolAddress((void**)&wint, g_wint);
    cudaGetSymbolAddress((void**)&wdtt, g_wdtt);
    cudaGetSymbolAddress((void**)&woutt, g_woutt);
    cudaGetSymbolAddress((void**)&wxt, g_wxt);
    cudaGetSymbolAddress((void**)&dtin, g_dtin);
    cudaGetSymbolAddress((void**)&xdbl, g_xdbl);
    cudaGetSymbolAddress((void**)&ht, g_ht);

    const int SMEM_BYTES = 98304;
    cudaFuncSetAttribute(tf32_gemm_v2, cudaFuncAttributeMaxDynamicSharedMemorySize,
                         SMEM_BYTES);

    // 0) tf32-round operands into scratch
    {
        int n4;
        n4 = MROWS * D_MODEL / 4;
        cvt_tf32_kernel<<<(n4 + 255) / 256, 256>>>((const float4*)x, (float4*)xt, n4);
        n4 = 2 * D_INNER * D_MODEL / 4;
        cvt_tf32_kernel<<<(n4 + 255) / 256, 256>>>((const float4*)W_in, (float4*)wint, n4);
        n4 = D_INNER * DT_RANK / 4;
        cvt_tf32_kernel<<<(n4 + 255) / 256, 256>>>((const float4*)W_dt, (float4*)wdtt, n4);
        n4 = D_MODEL * D_INNER / 4;
        cvt_tf32_kernel<<<(n4 + 255) / 256, 256>>>((const float4*)W_out, (float4*)woutt, n4);
        n4 = XDBL_N * D_INNER / 4;
        cvt_tf32_kernel<<<(n4 + 255) / 256, 256>>>((const float4*)W_x, (float4*)wxt, n4);
    }

    // 1) in_proj (TC tf32): xr[8192,3072] = xt @ wint^T
    tf32_gemm_v2<<<dim3(2 * D_INNER / 128, MROWS / 128), 256, SMEM_BYTES>>>(
        MROWS, 2 * D_INNER, D_MODEL, xt, D_MODEL, wint, D_MODEL, nullptr, xr, 0, nullptr);

    // 2) depthwise causal conv + silu -> g_h (fp32) + g_ht (tf32)
    conv_silu_kernel<<<(MROWS * D_INNER) / 256, 256>>>(conv_w, conv_b);

    // 3) x_proj (TC tf32): xdbl = ht @ wxt^T ; packs tf32 dt cols into g_dtin
    tf32_gemm_v2<<<dim3(1, MROWS / 128), 256, SMEM_BYTES>>>(
        MROWS, XDBL_N, D_INNER, ht, D_INNER, wxt, D_INNER, nullptr, xdbl, 0, dtin);

    // 4) dt_proj + softplus (TC tf32): delta = softplus(dtin @ wdtt^T + b_dt)
    tf32_gemm_v2<<<dim3(D_INNER / 128, MROWS / 128), 256, SMEM_BYTES>>>(
        MROWS, D_INNER, DT_RANK, dtin, DT_RANK, wdtt, DT_RANK, b_dt, delta, 1, nullptr);

    // 5) chunked parallel scan (3 phases) -> g_y (tf32-rounded)
    scan_phase1<<<dim3(D_INNER / 16, NBATCH, NC), 256>>>(A_log);
    scan_phase2<<<PLANE / 256, 256>>>();
    scan_phase3<<<dim3(D_INNER / 16, NBATCH, NC), 256>>>(A_log, Dp);

    // 6) out_proj (TC tf32): out = g_y @ woutt^T
    tf32_gemm_v2<<<dim3(D_MODEL / 128, MROWS / 128), 256, SMEM_BYTES>>>(
        MROWS, D_MODEL, D_INNER, y, D_INNER, woutt, D_INNER, nullptr, out, 0, nullptr);
}

// round 9
// speedup vs baseline: 2.7957x; 1.4209x over previous
#include <cuda_runtime.h>
#include <math.h>
#include <stdint.h>

#define D_MODEL 768
#define D_INNER 1536
#define NBATCH 4
#define LSEQ 2048
#define MROWS (NBATCH * LSEQ)      // 8192
#define DT_RANK 48
#define D_STATE 16
#define XDBL_N (DT_RANK + 2 * D_STATE)   // 80
#define NC 32                       // scan chunks
#define CL (LSEQ / NC)              // 64 steps per chunk
#define PLANE (NBATCH * D_INNER * D_STATE)   // 98304

// -------- scratch (device globals; no allocation allowed) --------
__device__ __align__(16) float g_xr[(size_t)MROWS * 2 * D_INNER];   // in_proj out
__device__ __align__(16) float g_h[(size_t)MROWS * D_INNER];        // conv+silu (fp32)
__device__ __align__(16) float g_ht[(size_t)MROWS * D_INNER];       // conv+silu (tf32)
__device__ __align__(16) float g_xdbl[(size_t)MROWS * XDBL_N];      // x_proj out
__device__ __align__(16) float g_dtin[(size_t)MROWS * DT_RANK];     // dt cols (tf32)
__device__ __align__(16) float g_du[(size_t)MROWS * D_INNER * 2];   // packed {delta, u}
__device__ __align__(16) float g_y[(size_t)MROWS * D_INNER];        // scan out (tf32)
// scan chunk summaries / incoming states, layout [c][b*D_INNER*16 + d*16 + n]
__device__ __align__(16) float g_ca[(size_t)NC * PLANE];
__device__ __align__(16) float g_cs[(size_t)NC * PLANE];
__device__ __align__(16) float g_hin[(size_t)NC * PLANE];
// tf32-rounded operand copies
__device__ __align__(16) float g_xt[(size_t)MROWS * D_MODEL];
__device__ __align__(16) float g_wint[(size_t)2 * D_INNER * D_MODEL];
__device__ __align__(16) float g_wdtt[(size_t)D_INNER * DT_RANK];
__device__ __align__(16) float g_woutt[(size_t)D_MODEL * D_INNER];
__device__ __align__(16) float g_wxt[(size_t)XDBL_N * D_INNER];

__device__ __forceinline__ float siluf(float v) { return v / (1.f + __expf(-v)); }
__device__ __forceinline__ float softplusf(float v) {
    return v > 20.f ? v : log1pf(__expf(v));
}
__device__ __forceinline__ unsigned f2tf32(float f) {
    unsigned u;
    asm("cvt.rna.tf32.f32 %0, %1;" : "=r"(u) : "f"(f));
    return u;
}
#define CP_COMMIT() asm volatile("cp.async.commit_group;" ::: "memory")
#define CP_WAIT1()  asm volatile("cp.async.wait_group 1;" ::: "memory")

__device__ __forceinline__ void cp16z(uint32_t s, const void* g, unsigned sz) {
    asm volatile("cp.async.cg.shared.global [%0], [%1], 16, %2;"
                 :: "r"(s), "l"(g), "r"(sz));
}

// ============================================================================
// Elementwise fp32 -> tf32(rna)-rounded copy (vectorized).
// ============================================================================
__global__ __launch_bounds__(256) void cvt_tf32_kernel(
    const float4* __restrict__ src, float4* __restrict__ dst, int n4)
{
    int i = blockIdx.x * 256 + threadIdx.x;
    if (i < n4) {
        float4 v = src[i];
        v.x = __uint_as_float(f2tf32(v.x));
        v.y = __uint_as_float(f2tf32(v.y));
        v.z = __uint_as_float(f2tf32(v.z));
        v.w = __uint_as_float(f2tf32(v.w));
        dst[i] = v;
    }
}

// ============================================================================
// TF32 tensor-core NT GEMM, 3-stage cp.async, 512 threads / 16 warps.
// C[M,N] = A[M,K]*B[N,K]^T (+bias, +activation). A,B pre-rounded to tf32.
// Req: M%128==0, K%4==0, lda/ldb%4==0. N arbitrary (zfill + store guards).
// Block 128x128, BK=32, 16 warps as 4(M)x4(N), warp tile 32x32 (acc 32 regs).
// smem stage = 32KB, 3 stages = 96KB. Swizzle: chunk ^= row&7.
// act: 0 = none; 1 = softplus; 2 = softplus + pack {v, g_h[r,c]} into C
//      (C = float2 array [M,N]). C2: packed tf32 copy of cols < DT_RANK.
// ============================================================================
__global__ __launch_bounds__(512) void tf32_gemm_v3(
    int M, int N, int K,
    const float* __restrict__ A, int lda,
    const float* __restrict__ B, int ldb,
    const float* __restrict__ bias,
    float* __restrict__ C, int act, float* __restrict__ C2)
{
    extern __shared__ __align__(16) char sm[];

    const int tid = threadIdx.x;
    const int lane = tid & 31;
    const int warp = tid >> 5;           // 0..15
    const int wm = (warp & 3) * 32;
    const int wn = (warp >> 2) * 32;
    const int row0 = blockIdx.y * 128;
    const int col0 = blockIdx.x * 128;
    const uint32_t smBase = (uint32_t)__cvta_generic_to_shared(sm);

    // cp.async: thread -> row (tid>>2), chunks {cj, cj+4} of 8 16B chunks/row
    const int crow = tid >> 2;
    const int cj = tid & 3;
    const float* gA = A + (size_t)(row0 + crow) * lda;
    const int browg = col0 + crow;
    const bool brval = browg < N;
    const float* gB = B + (size_t)(brval ? browg : 0) * ldb;
    uint32_t so[2];
#pragma unroll
    for (int t = 0; t < 2; t++)
        so[t] = (uint32_t)(crow * 128 + (((cj + 4 * t) ^ (crow & 7)) << 4));

    // ldmatrix per-lane offsets (stage-relative)
    const int g = lane >> 3;
    const int lrow = lane & 7;
    uint32_t aOff[4][2], bOff[4][2];
#pragma unroll
    for (int s = 0; s < 4; s++) {
        const int c16 = s * 2 + (g >> 1);
#pragma unroll
        for (int mi = 0; mi < 2; mi++) {
            int row = wm + mi * 16 + (g & 1) * 8 + lrow;
            aOff[s][mi] = (uint32_t)(row * 128 + ((c16 ^ (row & 7)) << 4));
        }
#pragma unroll
        for (int p = 0; p < 2; p++) {
            int row = wn + p * 16 + (g & 1) * 8 + lrow;
            bOff[s][p] = (uint32_t)(row * 128 + ((c16 ^ (row & 7)) << 4));
        }
    }

    float acc[2][4][4];
#pragma unroll
    for (int mi = 0; mi < 2; mi++)
#pragma unroll
        for (int ni = 0; ni < 4; ni++)
#pragma unroll
            for (int q = 0; q < 4; q++) acc[mi][ni][q] = 0.f;

    const int nIter = (K + 31) / 32;

#define ISSUE(it, st) do {                                                   \
        const uint32_t ab_ = smBase + (uint32_t)(st) * 32768u;                \
        const uint32_t bb_ = ab_ + 16384u;                                    \
        const int k0_ = (it) * 32;                                            \
        _Pragma("unroll")                                                     \
        for (int t = 0; t < 2; t++) {                                         \
            const int kc = k0_ + (cj + 4 * t) * 4;                            \
            const bool kv = kc < K;                                           \
            const int kcl = kv ? kc : 0;                                      \
            cp16z(ab_ + so[t], gA + kcl, kv ? 16u : 0u);                      \
            cp16z(bb_ + so[t], gB + kcl, (kv && brval) ? 16u : 0u);           \
        }                                                                     \
        CP_COMMIT();                                                          \
    } while (0)

#define LDFRAGS(sl, AF, BF, ab_, bb_) do {                                    \
        _Pragma("unroll")                                                     \
        for (int mi = 0; mi < 2; mi++)                                        \
            asm volatile("ldmatrix.sync.aligned.m8n8.x4.shared.b16 "          \
                         "{%0,%1,%2,%3}, [%4];"                               \
                         : "=r"(AF[mi][0]), "=r"(AF[mi][1]),                  \
                           "=r"(AF[mi][2]), "=r"(AF[mi][3])                   \
                         : "r"((ab_) + aOff[sl][mi]));                        \
        _Pragma("unroll")                                                     \
        for (int p = 0; p < 2; p++)                                           \
            asm volatile("ldmatrix.sync.aligned.m8n8.x4.shared.b16 "          \
                         "{%0,%1,%2,%3}, [%4];"                               \
                         : "=r"(BF[p][0]), "=r"(BF[p][1]),                    \
                           "=r"(BF[p][2]), "=r"(BF[p][3])                     \
                         : "r"((bb_) + bOff[sl][p]));                         \
    } while (0)

#define DO_MMA(AF, BF) do {                                                   \
        _Pragma("unroll")                                                     \
        for (int mi = 0; mi < 2; mi++)                                        \
            _Pragma("unroll")                                                 \
            for (int ni = 0; ni < 4; ni++) {                                  \
                unsigned bb0 = BF[ni >> 1][(ni & 1)];                         \
                unsigned bb1 = BF[ni >> 1][(ni & 1) + 2];                     \
                asm volatile(                                                 \
                    "mma.sync.aligned.m16n8k8.row.col.f32.tf32.tf32.f32 "     \
                    "{%0,%1,%2,%3}, {%4,%5,%6,%7}, {%8,%9}, {%0,%1,%2,%3};"   \
                    : "+f"(acc[mi][ni][0]), "+f"(acc[mi][ni][1]),             \
                      "+f"(acc[mi][ni][2]), "+f"(acc[mi][ni][3])              \
                    : "r"(AF[mi][0]), "r"(AF[mi][1]),                         \
                      "r"(AF[mi][2]), "r"(AF[mi][3]),                         \
                      "r"(bb0), "r"(bb1));                                    \
            }                                                                 \
    } while (0)

    ISSUE(0, 0);
    if (nIter > 1) ISSUE(1, 1);
    else CP_COMMIT();
    CP_WAIT1();
    __syncthreads();

    int cs = 0, is_ = 2;
    for (int it = 0; it < nIter; ++it) {
        if (it + 2 < nIter) ISSUE(it + 2, is_);
        else CP_COMMIT();

        const uint32_t ab = smBase + (uint32_t)cs * 32768u;
        const uint32_t bb = ab + 16384u;
        unsigned afr[2][2][4], bfr[2][2][4];
        LDFRAGS(0, afr[0], bfr[0], ab, bb);
#pragma unroll
        for (int s = 0; s < 4; s++) {
            const int cur = s & 1, nxt = cur ^ 1;
            if (s < 3) {
                switch (s + 1) {
                case 1: LDFRAGS(1, afr[nxt], bfr[nxt], ab, bb); break;
                case 2: LDFRAGS(2, afr[nxt], bfr[nxt], ab, bb); break;
                default: LDFRAGS(3, afr[nxt], bfr[nxt], ab, bb); break;
                }
            }
            DO_MMA(afr[cur], bfr[cur]);
        }

        CP_WAIT1();
        __syncthreads();
        cs = (cs == 2) ? 0 : cs + 1;
        is_ = (is_ == 2) ? 0 : is_ + 1;
    }
#undef ISSUE
#undef LDFRAGS
#undef DO_MMA

    // ---- epilogue
#pragma unroll
    for (int mi = 0; mi < 2; mi++) {
        const int r = row0 + wm + mi * 16 + (lane >> 2);
#pragma unroll
        for (int ni = 0; ni < 4; ni++) {
            const int c = col0 + wn + ni * 8 + (lane & 3) * 2;
            if (c < N) {
                float2 v0 = make_float2(acc[mi][ni][0], acc[mi][ni][1]);
                float2 v1 = make_float2(acc[mi][ni][2], acc[mi][ni][3]);
                if (bias) {
                    float b0 = bias[c], b1 = bias[c + 1];
                    v0.x += b0; v0.y += b1; v1.x += b0; v1.y += b1;
                }
                if (act >= 1) {
                    v0.x = softplusf(v0.x); v0.y = softplusf(v0.y);
                    v1.x = softplusf(v1.x); v1.y = softplusf(v1.y);
                }
                if (act == 2) {
                    // pack {delta, u}: C is float2 array [M, N]
                    float2 h0 = *(const float2*)&g_h[(size_t)r * N + c];
                    float2 h1 = *(const float2*)&g_h[(size_t)(r + 8) * N + c];
                    *(float4*)&C[2 * ((size_t)r * N + c)] =
                        make_float4(v0.x, h0.x, v0.y, h0.y);
                    *(float4*)&C[2 * ((size_t)(r + 8) * N + c)] =
                        make_float4(v1.x, h1.x, v1.y, h1.y);
                } else {
                    *(float2*)&C[(size_t)r * N + c] = v0;
                    *(float2*)&C[(size_t)(r + 8) * N + c] = v1;
                }
                if (C2 && c < DT_RANK) {
                    float* d0 = C2 + (size_t)r * DT_RANK + c;
                    float* d1 = C2 + (size_t)(r + 8) * DT_RANK + c;
                    d0[0] = __uint_as_float(f2tf32(v0.x));
                    d0[1] = __uint_as_float(f2tf32(v0.y));
                    d1[0] = __uint_as_float(f2tf32(v1.x));
                    d1[1] = __uint_as_float(f2tf32(v1.y));
                }
            }
        }
    }
}

// ============================================================================
// Depthwise causal conv1d (d_conv=4) + bias + SiLU; fp32 + tf32 copies.
// ============================================================================
__global__ __launch_bounds__(256) void conv_silu_kernel(
    const float* __restrict__ cw, const float* __restrict__ cb)
{
    const int idx = blockIdx.x * 256 + threadIdx.x;
    const int d = idx % D_INNER;
    const int m = idx / D_INNER;
    const int l = m & (LSEQ - 1);
    const float* base = g_xr + (size_t)m * (2 * D_INNER) + d;
    float acc = cb[d];
#pragma unroll
    for (int j = 0; j < 4; j++) {
        const int ll = l - 3 + j;
        if (ll >= 0)
            acc = fmaf(cw[d * 4 + j], base[(ptrdiff_t)(j - 3) * (2 * D_INNER)], acc);
    }
    const float hv = siluf(acc);
    g_h[idx] = hv;
    g_ht[idx] = __uint_as_float(f2tf32(hv));
}

// ============================================================================
// Chunked parallel selective scan.
// Thread = (b, d, state-pair p -> states 2p,2p+1, chunk); 8 lanes/channel,
// warp = 4 channels; block = 32 channels. Grid (D_INNER/32, NBATCH, NC).
// ============================================================================
__global__ __launch_bounds__(256) void scan_phase1(const float* __restrict__ A_log)
{
    const int lane = threadIdx.x & 31;
    const int warp = threadIdx.x >> 5;
    const int p = lane & 7;
    const int d = blockIdx.x * 32 + warp * 4 + (lane >> 3);
    const int b = blockIdx.y;
    const int c = blockIdx.z;
    const int t0 = c * CL;

    const float LOG2E = 1.4426950408889634f;
    const float Alg0 = -__expf(A_log[d * D_STATE + 2 * p]) * LOG2E;
    const float Alg1 = -__expf(A_log[d * D_STATE + 2 * p + 1]) * LOG2E;
    float s0 = 0.f, s1 = 0.f, dtsum = 0.f;

    const float2* dup = (const float2*)(g_du + 2 * (((size_t)b * LSEQ + t0) * D_INNER + d));
    const float2* Bp = (const float2*)(g_xdbl + ((size_t)b * LSEQ + t0) * XDBL_N
                                       + DT_RANK + 2 * p);

#pragma unroll 4
    for (int t = 0; t < CL; t++) {
        const float2 duv = __ldg(dup);
        const float2 Bv = __ldg(Bp);
        const float dt = duv.x;
        const float du_ = dt * duv.y;
        dtsum += dt;
        s0 = fmaf(exp2f(dt * Alg0), s0, du_ * Bv.x);
        s1 = fmaf(exp2f(dt * Alg1), s1, du_ * Bv.y);
        dup += D_INNER;
        Bp += XDBL_N / 2;
    }

    const size_t idx = (size_t)c * PLANE + (((size_t)b * D_INNER + d) << 4) + 2 * p;
    *(float2*)&g_ca[idx] = make_float2(exp2f(Alg0 * dtsum), exp2f(Alg1 * dtsum));
    *(float2*)&g_cs[idx] = make_float2(s0, s1);
}

// ============================================================================
// Phase 2: exclusive scan over chunk summaries. Thread = (b,d,n).
// ============================================================================
__global__ __launch_bounds__(256) void scan_phase2()
{
    const size_t i = (size_t)blockIdx.x * 256 + threadIdx.x;
    float h = 0.f;
#pragma unroll
    for (int c = 0; c < NC; c++) {
        const size_t o = (size_t)c * PLANE + i;
        g_hin[o] = h;
        h = fmaf(g_ca[o], h, g_cs[o]);
    }
}

// ============================================================================
// Phase 3: re-run each chunk from its incoming state, fused with C-reduction,
// +u*D residual, *silu(res) gating; writes y tf32-rounded.
// ============================================================================
__global__ __launch_bounds__(256) void scan_phase3(
    const float* __restrict__ A_log, const float* __restrict__ Dp)
{
    const int lane = threadIdx.x & 31;
    const int warp = threadIdx.x >> 5;
    const int p = lane & 7;
    const int d = blockIdx.x * 32 + warp * 4 + (lane >> 3);
    const int b = blockIdx.y;
    const int c = blockIdx.z;
    const int t0 = c * CL;

    const float LOG2E = 1.4426950408889634f;
    const float Alg0 = -__expf(A_log[d * D_STATE + 2 * p]) * LOG2E;
    const float Alg1 = -__expf(A_log[d * D_STATE + 2 * p + 1]) * LOG2E;
    const float Dd = Dp[d];

    const size_t idx = (size_t)c * PLANE + (((size_t)b * D_INNER + d) << 4) + 2 * p;
    float2 st = *(const float2*)&g_hin[idx];
    float s0 = st.x, s1 = st.y;

    const float2* dup = (const float2*)(g_du + 2 * (((size_t)b * LSEQ + t0) * D_INNER + d));
    const float2* Bp = (const float2*)(g_xdbl + ((size_t)b * LSEQ + t0) * XDBL_N
                                       + DT_RANK + 2 * p);
    const float2* Cp = (const float2*)(g_xdbl + ((size_t)b * LSEQ + t0) * XDBL_N
                                       + DT_RANK + D_STATE + 2 * p);
    const float* rptr = g_xr + ((size_t)b * LSEQ + t0) * (2 * D_INNER) + D_INNER + d;
    float* yptr = g_y + ((size_t)b * LSEQ + t0) * D_INNER + d;

#pragma unroll 4
    for (int t = 0; t < CL; t++) {
        const float2 duv = __ldg(dup);
        const float2 Bv = __ldg(Bp);
        const float2 Cv = __ldg(Cp);
        const float dt = duv.x;
        const float ut = duv.y;
        const float du_ = dt * ut;

        s0 = fmaf(exp2f(dt * Alg0), s0, du_ * Bv.x);
        s1 = fmaf(exp2f(dt * Alg1), s1, du_ * Bv.y);

        float sp = s0 * Cv.x + s1 * Cv.y;
        sp += __shfl_xor_sync(0xffffffffu, sp, 1);
        sp += __shfl_xor_sync(0xffffffffu, sp, 2);
        sp += __shfl_xor_sync(0xffffffffu, sp, 4);

        if (p == 0) {
            const float rv = __ldg(rptr);
            *yptr = __uint_as_float(f2tf32((sp + ut * Dd) * siluf(rv)));
        }
        dup += D_INNER;
        Bp += XDBL_N / 2;
        Cp += XDBL_N / 2;
        rptr += 2 * D_INNER;
        yptr += D_INNER;
    }
}

// ============================================================================
// kernel_launch
// Inputs: x, W_in, conv_w, conv_b, W_x, W_dt, b_dt, A_log, D, W_out
// ============================================================================
extern "C" void kernel_launch(void* const* d_in, const int* in_sizes, int n_in,
                              void* d_out, int out_size)
{
    const float* x      = (const float*)d_in[0];
    const float* W_in   = (const float*)d_in[1];
    const float* conv_w = (const float*)d_in[2];
    const float* conv_b = (const float*)d_in[3];
    const float* W_x    = (const float*)d_in[4];
    const float* W_dt   = (const float*)d_in[5];
    const float* b_dt   = (const float*)d_in[6];
    const float* A_log  = (const float*)d_in[7];
    const float* Dp     = (const float*)d_in[8];
    const float* W_out  = (const float*)d_in[9];
    float* out = (float*)d_out;

    float *xr, *y, *xt, *wint, *wdtt, *woutt, *wxt, *dtin, *xdbl, *ht, *du;
    cudaGetSymbolAddress((void**)&xr, g_xr);
    cudaGetSymbolAddress((void**)&y, g_y);
    cudaGetSymbolAddress((void**)&xt, g_xt);
    cudaGetSymbolAddress((void**)&wint, g_wint);
    cudaGetSymbolAddress((void**)&wdtt, g_wdtt);
    cudaGetSymbolAddress((void**)&woutt, g_woutt);
    cudaGetSymbolAddress((void**)&wxt, g_wxt);
    cudaGetSymbolAddress((void**)&dtin, g_dtin);
    cudaGetSymbolAddress((void**)&xdbl, g_xdbl);
    cudaGetSymbolAddress((void**)&ht, g_ht);
    cudaGetSymbolAddress((void**)&du, g_du);

    const int SMEM_BYTES = 98304;
    cudaFuncSetAttribute(tf32_gemm_v3, cudaFuncAttributeMaxDynamicSharedMemorySize,
                         SMEM_BYTES);

    // 0) tf32-round operands into scratch
    {
        int n4;
        n4 = MROWS * D_MODEL / 4;
        cvt_tf32_kernel<<<(n4 + 255) / 256, 256>>>((const float4*)x, (float4*)xt, n4);
        n4 = 2 * D_INNER * D_MODEL / 4;
        cvt_tf32_kernel<<<(n4 + 255) / 256, 256>>>((const float4*)W_in, (float4*)wint, n4);
        n4 = D_INNER * DT_RANK / 4;
        cvt_tf32_kernel<<<(n4 + 255) / 256, 256>>>((const float4*)W_dt, (float4*)wdtt, n4);
        n4 = D_MODEL * D_INNER / 4;
        cvt_tf32_kernel<<<(n4 + 255) / 256, 256>>>((const float4*)W_out, (float4*)woutt, n4);
        n4 = XDBL_N * D_INNER / 4;
        cvt_tf32_kernel<<<(n4 + 255) / 256, 256>>>((const float4*)W_x, (float4*)wxt, n4);
    }

    // 1) in_proj (TC tf32): xr[8192,3072] = xt @ wint^T
    tf32_gemm_v3<<<dim3(2 * D_INNER / 128, MROWS / 128), 512, SMEM_BYTES>>>(
        MROWS, 2 * D_INNER, D_MODEL, xt, D_MODEL, wint, D_MODEL, nullptr, xr, 0, nullptr);

    // 2) depthwise causal conv + silu -> g_h (fp32) + g_ht (tf32)
    conv_silu_kernel<<<(MROWS * D_INNER) / 256, 256>>>(conv_w, conv_b);

    // 3) x_proj (TC tf32): xdbl = ht @ wxt^T ; packs tf32 dt cols into g_dtin
    tf32_gemm_v3<<<dim3(1, MROWS / 128), 512, SMEM_BYTES>>>(
        MROWS, XDBL_N, D_INNER, ht, D_INNER, wxt, D_INNER, nullptr, xdbl, 0, dtin);

    // 4) dt_proj + softplus (TC tf32), packing {delta, u} float2 -> g_du
    tf32_gemm_v3<<<dim3(D_INNER / 128, MROWS / 128), 512, SMEM_BYTES>>>(
        MROWS, D_INNER, DT_RANK, dtin, DT_RANK, wdtt, DT_RANK, b_dt, du, 2, nullptr);

    // 5) chunked parallel scan (3 phases) -> g_y (tf32-rounded)
    scan_phase1<<<dim3(D_INNER / 32, NBATCH, NC), 256>>>(A_log);
    scan_phase2<<<PLANE / 256, 256>>>();
    scan_phase3<<<dim3(D_INNER / 32, NBATCH, NC), 256>>>(A_log, Dp);

    // 6) out_proj (TC tf32): out = g_y @ woutt^T
    tf32_gemm_v3<<<dim3(D_MODEL / 128, MROWS / 128), 512, SMEM_BYTES>>>(
        MROWS, D_MODEL, D_INNER, y, D_INNER, woutt, D_INNER, nullptr, out, 0, nullptr);
}

// round 10
// speedup vs baseline: 3.0180x; 1.0795x over previous
#include <cuda_runtime.h>
#include <math.h>
#include <stdint.h>

#define D_MODEL 768
#define D_INNER 1536
#define NBATCH 4
#define LSEQ 2048
#define MROWS (NBATCH * LSEQ)      // 8192
#define DT_RANK 48
#define D_STATE 16
#define XDBL_N (DT_RANK + 2 * D_STATE)   // 80
#define NC 32                       // scan chunks
#define CL (LSEQ / NC)              // 64 steps per chunk
#define DBLK 32                     // channels per scan block
#define CHAINS (NBATCH * (D_INNER / DBLK))   // 192 look-back chains

// -------- scratch (device globals; no allocation allowed) --------
__device__ __align__(16) float g_xr[(size_t)MROWS * 2 * D_INNER];   // in_proj out
__device__ __align__(16) float g_h[(size_t)MROWS * D_INNER];        // conv+silu (fp32)
__device__ __align__(16) float g_ht[(size_t)MROWS * D_INNER];       // conv+silu (tf32)
__device__ __align__(16) float g_xdbl[(size_t)MROWS * XDBL_N];      // x_proj out
__device__ __align__(16) float g_dtin[(size_t)MROWS * DT_RANK];     // dt cols (tf32)
__device__ __align__(16) float g_du[(size_t)MROWS * D_INNER * 2];   // packed {delta, u}
__device__ __align__(16) float g_y[(size_t)MROWS * D_INNER];        // scan out (tf32)
// decoupled look-back state: inclusive chunk states + ready flags
__device__ __align__(16) float g_inc[(size_t)CHAINS * NC * (DBLK * D_STATE)];
__device__ int g_flags[CHAINS * NC];
// tf32-rounded operand copies
__device__ __align__(16) float g_xt[(size_t)MROWS * D_MODEL];
__device__ __align__(16) float g_wint[(size_t)2 * D_INNER * D_MODEL];
__device__ __align__(16) float g_wdtt[(size_t)D_INNER * DT_RANK];
__device__ __align__(16) float g_woutt[(size_t)D_MODEL * D_INNER];
__device__ __align__(16) float g_wxt[(size_t)XDBL_N * D_INNER];

__device__ __forceinline__ float siluf(float v) { return v / (1.f + __expf(-v)); }
__device__ __forceinline__ float softplusf(float v) {
    return v > 20.f ? v : log1pf(__expf(v));
}
__device__ __forceinline__ unsigned f2tf32(float f) {
    unsigned u;
    asm("cvt.rna.tf32.f32 %0, %1;" : "=r"(u) : "f"(f));
    return u;
}
#define CP_COMMIT() asm volatile("cp.async.commit_group;" ::: "memory")
#define CP_WAIT1()  asm volatile("cp.async.wait_group 1;" ::: "memory")

__device__ __forceinline__ void cp16z(uint32_t s, const void* g, unsigned sz) {
    asm volatile("cp.async.cg.shared.global [%0], [%1], 16, %2;"
                 :: "r"(s), "l"(g), "r"(sz));
}

// ============================================================================
// Elementwise fp32 -> tf32(rna)-rounded copy (vectorized).
// ============================================================================
__global__ __launch_bounds__(256) void cvt_tf32_kernel(
    const float4* __restrict__ src, float4* __restrict__ dst, int n4)
{
    int i = blockIdx.x * 256 + threadIdx.x;
    if (i < n4) {
        float4 v = src[i];
        v.x = __uint_as_float(f2tf32(v.x));
        v.y = __uint_as_float(f2tf32(v.y));
        v.z = __uint_as_float(f2tf32(v.z));
        v.w = __uint_as_float(f2tf32(v.w));
        dst[i] = v;
    }
}

// ============================================================================
// TF32 tensor-core NT GEMM, 3-stage cp.async, 512 threads / 16 warps.
// (unchanged from R9 — proven at 1064us total)
// ============================================================================
__global__ __launch_bounds__(512) void tf32_gemm_v3(
    int M, int N, int K,
    const float* __restrict__ A, int lda,
    const float* __restrict__ B, int ldb,
    const float* __restrict__ bias,
    float* __restrict__ C, int act, float* __restrict__ C2)
{
    extern __shared__ __align__(16) char sm[];

    const int tid = threadIdx.x;
    const int lane = tid & 31;
    const int warp = tid >> 5;           // 0..15
    const int wm = (warp & 3) * 32;
    const int wn = (warp >> 2) * 32;
    const int row0 = blockIdx.y * 128;
    const int col0 = blockIdx.x * 128;
    const uint32_t smBase = (uint32_t)__cvta_generic_to_shared(sm);

    const int crow = tid >> 2;
    const int cj = tid & 3;
    const float* gA = A + (size_t)(row0 + crow) * lda;
    const int browg = col0 + crow;
    const bool brval = browg < N;
    const float* gB = B + (size_t)(brval ? browg : 0) * ldb;
    uint32_t so[2];
#pragma unroll
    for (int t = 0; t < 2; t++)
        so[t] = (uint32_t)(crow * 128 + (((cj + 4 * t) ^ (crow & 7)) << 4));

    const int g = lane >> 3;
    const int lrow = lane & 7;
    uint32_t aOff[4][2], bOff[4][2];
#pragma unroll
    for (int s = 0; s < 4; s++) {
        const int c16 = s * 2 + (g >> 1);
#pragma unroll
        for (int mi = 0; mi < 2; mi++) {
            int row = wm + mi * 16 + (g & 1) * 8 + lrow;
            aOff[s][mi] = (uint32_t)(row * 128 + ((c16 ^ (row & 7)) << 4));
        }
#pragma unroll
        for (int p = 0; p < 2; p++) {
            int row = wn + p * 16 + (g & 1) * 8 + lrow;
            bOff[s][p] = (uint32_t)(row * 128 + ((c16 ^ (row & 7)) << 4));
        }
    }

    float acc[2][4][4];
#pragma unroll
    for (int mi = 0; mi < 2; mi++)
#pragma unroll
        for (int ni = 0; ni < 4; ni++)
#pragma unroll
            for (int q = 0; q < 4; q++) acc[mi][ni][q] = 0.f;

    const int nIter = (K + 31) / 32;

#define ISSUE(it, st) do {                                                   \
        const uint32_t ab_ = smBase + (uint32_t)(st) * 32768u;                \
        const uint32_t bb_ = ab_ + 16384u;                                    \
        const int k0_ = (it) * 32;                                            \
        _Pragma("unroll")                                                     \
        for (int t = 0; t < 2; t++) {                                         \
            const int kc = k0_ + (cj + 4 * t) * 4;                            \
            const bool kv = kc < K;                                           \
            const int kcl = kv ? kc : 0;                                      \
            cp16z(ab_ + so[t], gA + kcl, kv ? 16u : 0u);                      \
            cp16z(bb_ + so[t], gB + kcl, (kv && brval) ? 16u : 0u);           \
        }                                                                     \
        CP_COMMIT();                                                          \
    } while (0)

#define LDFRAGS(sl, AF, BF, ab_, bb_) do {                                    \
        _Pragma("unroll")                                                     \
        for (int mi = 0; mi < 2; mi++)                                        \
            asm volatile("ldmatrix.sync.aligned.m8n8.x4.shared.b16 "          \
                         "{%0,%1,%2,%3}, [%4];"                               \
                         : "=r"(AF[mi][0]), "=r"(AF[mi][1]),                  \
                           "=r"(AF[mi][2]), "=r"(AF[mi][3])                   \
                         : "r"((ab_) + aOff[sl][mi]));                        \
        _Pragma("unroll")                                                     \
        for (int p = 0; p < 2; p++)                                           \
            asm volatile("ldmatrix.sync.aligned.m8n8.x4.shared.b16 "          \
                         "{%0,%1,%2,%3}, [%4];"                               \
                         : "=r"(BF[p][0]), "=r"(BF[p][1]),                    \
                           "=r"(BF[p][2]), "=r"(BF[p][3])                     \
                         : "r"((bb_) + bOff[sl][p]));                         \
    } while (0)

#define DO_MMA(AF, BF) do {                                                   \
        _Pragma("unroll")                                                     \
        for (int mi = 0; mi < 2; mi++)                                        \
            _Pragma("unroll")                                                 \
            for (int ni = 0; ni < 4; ni++) {                                  \
                unsigned bb0 = BF[ni >> 1][(ni & 1)];                         \
                unsigned bb1 = BF[ni >> 1][(ni & 1) + 2];                     \
                asm volatile(                                                 \
                    "mma.sync.aligned.m16n8k8.row.col.f32.tf32.tf32.f32 "     \
                    "{%0,%1,%2,%3}, {%4,%5,%6,%7}, {%8,%9}, {%0,%1,%2,%3};"   \
                    : "+f"(acc[mi][ni][0]), "+f"(acc[mi][ni][1]),             \
                      "+f"(acc[mi][ni][2]), "+f"(acc[mi][ni][3])              \
                    : "r"(AF[mi][0]), "r"(AF[mi][1]),                         \
                      "r"(AF[mi][2]), "r"(AF[mi][3]),                         \
                      "r"(bb0), "r"(bb1));                                    \
            }                                                                 \
    } while (0)

    ISSUE(0, 0);
    if (nIter > 1) ISSUE(1, 1);
    else CP_COMMIT();
    CP_WAIT1();
    __syncthreads();

    int cs = 0, is_ = 2;
    for (int it = 0; it < nIter; ++it) {
        if (it + 2 < nIter) ISSUE(it + 2, is_);
        else CP_COMMIT();

        const uint32_t ab = smBase + (uint32_t)cs * 32768u;
        const uint32_t bb = ab + 16384u;
        unsigned afr[2][2][4], bfr[2][2][4];
        LDFRAGS(0, afr[0], bfr[0], ab, bb);
#pragma unroll
        for (int s = 0; s < 4; s++) {
            const int cur = s & 1, nxt = cur ^ 1;
            if (s < 3) {
                switch (s + 1) {
                case 1: LDFRAGS(1, afr[nxt], bfr[nxt], ab, bb); break;
                case 2: LDFRAGS(2, afr[nxt], bfr[nxt], ab, bb); break;
                default: LDFRAGS(3, afr[nxt], bfr[nxt], ab, bb); break;
                }
            }
            DO_MMA(afr[cur], bfr[cur]);
        }

        CP_WAIT1();
        __syncthreads();
        cs = (cs == 2) ? 0 : cs + 1;
        is_ = (is_ == 2) ? 0 : is_ + 1;
    }
#undef ISSUE
#undef LDFRAGS
#undef DO_MMA

    // ---- epilogue
#pragma unroll
    for (int mi = 0; mi < 2; mi++) {
        const int r = row0 + wm + mi * 16 + (lane >> 2);
#pragma unroll
        for (int ni = 0; ni < 4; ni++) {
            const int c = col0 + wn + ni * 8 + (lane & 3) * 2;
            if (c < N) {
                float2 v0 = make_float2(acc[mi][ni][0], acc[mi][ni][1]);
                float2 v1 = make_float2(acc[mi][ni][2], acc[mi][ni][3]);
                if (bias) {
                    float b0 = bias[c], b1 = bias[c + 1];
                    v0.x += b0; v0.y += b1; v1.x += b0; v1.y += b1;
                }
                if (act >= 1) {
                    v0.x = softplusf(v0.x); v0.y = softplusf(v0.y);
                    v1.x = softplusf(v1.x); v1.y = softplusf(v1.y);
                }
                if (act == 2) {
                    float2 h0 = *(const float2*)&g_h[(size_t)r * N + c];
                    float2 h1 = *(const float2*)&g_h[(size_t)(r + 8) * N + c];
                    *(float4*)&C[2 * ((size_t)r * N + c)] =
                        make_float4(v0.x, h0.x, v0.y, h0.y);
                    *(float4*)&C[2 * ((size_t)(r + 8) * N + c)] =
                        make_float4(v1.x, h1.x, v1.y, h1.y);
                } else {
                    *(float2*)&C[(size_t)r * N + c] = v0;
                    *(float2*)&C[(size_t)(r + 8) * N + c] = v1;
                }
                if (C2 && c < DT_RANK) {
                    float* d0 = C2 + (size_t)r * DT_RANK + c;
                    float* d1 = C2 + (size_t)(r + 8) * DT_RANK + c;
                    d0[0] = __uint_as_float(f2tf32(v0.x));
                    d0[1] = __uint_as_float(f2tf32(v0.y));
                    d1[0] = __uint_as_float(f2tf32(v1.x));
                    d1[1] = __uint_as_float(f2tf32(v1.y));
                }
            }
        }
    }
}

// ============================================================================
// Depthwise causal conv1d (d_conv=4) + bias + SiLU; fp32 + tf32 copies.
// ============================================================================
__global__ __launch_bounds__(256) void conv_silu_kernel(
    const float* __restrict__ cw, const float* __restrict__ cb)
{
    const int idx = blockIdx.x * 256 + threadIdx.x;
    const int d = idx % D_INNER;
    const int m = idx / D_INNER;
    const int l = m & (LSEQ - 1);
    const float* base = g_xr + (size_t)m * (2 * D_INNER) + d;
    float acc = cb[d];
#pragma unroll
    for (int j = 0; j < 4; j++) {
        const int ll = l - 3 + j;
        if (ll >= 0)
            acc = fmaf(cw[d * 4 + j], base[(ptrdiff_t)(j - 3) * (2 * D_INNER)], acc);
    }
    const float hv = siluf(acc);
    g_h[idx] = hv;
    g_ht[idx] = __uint_as_float(f2tf32(hv));
}

// ============================================================================
// Zero look-back flags (must run before scan_fused on every launch/replay).
// ============================================================================
__global__ __launch_bounds__(256) void zero_flags_kernel()
{
    const int i = blockIdx.x * 256 + threadIdx.x;
    if (i < CHAINS * NC) g_flags[i] = 0;
}

// ============================================================================
// Single-pass selective scan with decoupled look-back.
// Block = (chunk c, dblk of 32 channels, batch b); blockIdx.x = c (dispatch-
// minor so predecessors are scheduled first). Inputs staged once in smem;
// summary scan -> publish inclusive chunk state -> spin on chunk c-1 ->
// final pass from smem fused with C-dot, +u*D, *silu(res); y staged in smem
// and written coalesced. Arithmetic order identical to the 3-phase version.
// ============================================================================
__global__ __launch_bounds__(256) void scan_fused(
    const float* __restrict__ A_log, const float* __restrict__ Dp)
{
    __shared__ float s_du[CL][64];    // {dt,u} per (t, channel)   16KB
    __shared__ float s_bc[CL][32];    // {B[16], C[16]} per t       8KB
    __shared__ float s_res[CL][32];   // res per (t, channel)       8KB
    __shared__ float s_y[CL][32];     // staged output              8KB

    const int c = blockIdx.x;
    const int dblk = blockIdx.y;
    const int b = blockIdx.z;
    const int tid = threadIdx.x;
    const int lane = tid & 31;
    const int warp = tid >> 5;
    const int p = lane & 7;               // state pair 2p, 2p+1
    const int dl = warp * 4 + (lane >> 3);  // local channel 0..31
    const int d0 = dblk * DBLK;
    const int d = d0 + dl;
    const size_t rowb = (size_t)b * LSEQ + (size_t)c * CL;

    // ---- cooperative staging (all coalesced float4)
    for (int i = tid; i < CL * 16; i += 256) {
        const int t = i >> 4, j = i & 15;
        *(float4*)&s_du[t][j * 4] =
            *(const float4*)(g_du + 2 * ((rowb + t) * D_INNER + d0) + j * 4);
    }
    for (int i = tid; i < CL * 8; i += 256) {
        const int t = i >> 3, j = i & 7;
        *(float4*)&s_bc[t][j * 4] =
            *(const float4*)(g_xdbl + (rowb + t) * XDBL_N + DT_RANK + j * 4);
    }
    for (int i = tid; i < CL * 8; i += 256) {
        const int t = i >> 3, j = i & 7;
        *(float4*)&s_res[t][j * 4] =
            *(const float4*)(g_xr + (rowb + t) * (2 * D_INNER) + D_INNER + d0 + j * 4);
    }
    __syncthreads();

    const float LOG2E = 1.4426950408889634f;
    const float Alg0 = -__expf(A_log[d * D_STATE + 2 * p]) * LOG2E;
    const float Alg1 = -__expf(A_log[d * D_STATE + 2 * p + 1]) * LOG2E;

    // ---- summary scan (local, from zero)
    float s0 = 0.f, s1 = 0.f, dtsum = 0.f;
#pragma unroll 4
    for (int t = 0; t < CL; t++) {
        const float dt = s_du[t][2 * dl];
        const float du_ = dt * s_du[t][2 * dl + 1];
        dtsum += dt;
        s0 = fmaf(exp2f(dt * Alg0), s0, du_ * s_bc[t][2 * p]);
        s1 = fmaf(exp2f(dt * Alg1), s1, du_ * s_bc[t][2 * p + 1]);
    }
    const float a0 = exp2f(Alg0 * dtsum);
    const float a1 = exp2f(Alg1 * dtsum);

    // ---- decoupled look-back (depth 1, inclusive propagation)
    const int chain = b * (D_INNER / DBLK) + dblk;
    float h0 = 0.f, h1 = 0.f;
    if (c > 0) {
        if (tid == 0) {
            while (atomicAdd(&g_flags[chain * NC + c - 1], 0) == 0) { }
        }
        __syncthreads();
        __threadfence();
        const float2 pv = *(const float2*)
            &g_inc[((size_t)chain * NC + c - 1) * (DBLK * D_STATE) + dl * 16 + 2 * p];
        h0 = pv.x; h1 = pv.y;
    }
    *(float2*)&g_inc[((size_t)chain * NC + c) * (DBLK * D_STATE) + dl * 16 + 2 * p] =
        make_float2(fmaf(a0, h0, s0), fmaf(a1, h1, s1));
    __threadfence();
    __syncthreads();
    if (tid == 0) atomicExch(&g_flags[chain * NC + c], 1);

    // ---- final pass from exclusive incoming state (h0, h1)
    const float Dd = Dp[d];
    s0 = h0; s1 = h1;
#pragma unroll 4
    for (int t = 0; t < CL; t++) {
        const float dt = s_du[t][2 * dl];
        const float ut = s_du[t][2 * dl + 1];
        const float du_ = dt * ut;
        s0 = fmaf(exp2f(dt * Alg0), s0, du_ * s_bc[t][2 * p]);
        s1 = fmaf(exp2f(dt * Alg1), s1, du_ * s_bc[t][2 * p + 1]);

        float sp = s0 * s_bc[t][16 + 2 * p] + s1 * s_bc[t][16 + 2 * p + 1];
        sp += __shfl_xor_sync(0xffffffffu, sp, 1);
        sp += __shfl_xor_sync(0xffffffffu, sp, 2);
        sp += __shfl_xor_sync(0xffffffffu, sp, 4);

        if (p == 0)
            s_y[t][dl] = __uint_as_float(
                f2tf32((sp + ut * Dd) * siluf(s_res[t][dl])));
    }
    __syncthreads();
    for (int i = tid; i < CL * 8; i += 256) {
        const int t = i >> 3, j = i & 7;
        *(float4*)(g_y + (rowb + t) * D_INNER + d0 + j * 4) = *(float4*)&s_y[t][j * 4];
    }
}

// ============================================================================
// kernel_launch
// Inputs: x, W_in, conv_w, conv_b, W_x, W_dt, b_dt, A_log, D, W_out
// Launch order puts in_proj at physical index 3 (the ncu-captured slot).
// ============================================================================
extern "C" void kernel_launch(void* const* d_in, const int* in_sizes, int n_in,
                              void* d_out, int out_size)
{
    const float* x      = (const float*)d_in[0];
    const float* W_in   = (const float*)d_in[1];
    const float* conv_w = (const float*)d_in[2];
    const float* conv_b = (const float*)d_in[3];
    const float* W_x    = (const float*)d_in[4];
    const float* W_dt   = (const float*)d_in[5];
    const float* b_dt   = (const float*)d_in[6];
    const float* A_log  = (const float*)d_in[7];
    const float* Dp     = (const float*)d_in[8];
    const float* W_out  = (const float*)d_in[9];
    float* out = (float*)d_out;

    float *xr, *y, *xt, *wint, *wdtt, *woutt, *wxt, *dtin, *xdbl, *ht, *du;
    cudaGetSymbolAddress((void**)&xr, g_xr);
    cudaGetSymbolAddress((void**)&y, g_y);
    cudaGetSymbolAddress((void**)&xt, g_xt);
    cudaGetSymbolAddress((void**)&wint, g_wint);
    cudaGetSymbolAddress((void**)&wdtt, g_wdtt);
    cudaGetSymbolAddress((void**)&woutt, g_woutt);
    cudaGetSymbolAddress((void**)&wxt, g_wxt);
    cudaGetSymbolAddress((void**)&dtin, g_dtin);
    cudaGetSymbolAddress((void**)&xdbl, g_xdbl);
    cudaGetSymbolAddress((void**)&ht, g_ht);
    cudaGetSymbolAddress((void**)&du, g_du);

    const int SMEM_BYTES = 98304;
    cudaFuncSetAttribute(tf32_gemm_v3, cudaFuncAttributeMaxDynamicSharedMemorySize,
                         SMEM_BYTES);

    int n4;
    // idx 0-2: cvts needed before in_proj / dt_proj
    n4 = MROWS * D_MODEL / 4;
    cvt_tf32_kernel<<<(n4 + 255) / 256, 256>>>((const float4*)x, (float4*)xt, n4);
    n4 = 2 * D_INNER * D_MODEL / 4;
    cvt_tf32_kernel<<<(n4 + 255) / 256, 256>>>((const float4*)W_in, (float4*)wint, n4);
    n4 = D_INNER * DT_RANK / 4;
    cvt_tf32_kernel<<<(n4 + 255) / 256, 256>>>((const float4*)W_dt, (float4*)wdtt, n4);

    // idx 3 (ncu capture slot): in_proj (TC tf32): xr = xt @ wint^T
    tf32_gemm_v3<<<dim3(2 * D_INNER / 128, MROWS / 128), 512, SMEM_BYTES>>>(
        MROWS, 2 * D_INNER, D_MODEL, xt, D_MODEL, wint, D_MODEL, nullptr, xr, 0, nullptr);

    // idx 4: depthwise causal conv + silu -> g_h (fp32) + g_ht (tf32)
    conv_silu_kernel<<<(MROWS * D_INNER) / 256, 256>>>(conv_w, conv_b);

    // idx 5-6: remaining weight cvts (needed by x_proj / out_proj)
    n4 = XDBL_N * D_INNER / 4;
    cvt_tf32_kernel<<<(n4 + 255) / 256, 256>>>((const float4*)W_x, (float4*)wxt, n4);
    n4 = D_MODEL * D_INNER / 4;
    cvt_tf32_kernel<<<(n4 + 255) / 256, 256>>>((const float4*)W_out, (float4*)woutt, n4);

    // idx 7: x_proj (TC tf32): xdbl = ht @ wxt^T ; packs tf32 dt cols -> dtin
    tf32_gemm_v3<<<dim3(1, MROWS / 128), 512, SMEM_BYTES>>>(
        MROWS, XDBL_N, D_INNER, ht, D_INNER, wxt, D_INNER, nullptr, xdbl, 0, dtin);

    // idx 8: dt_proj + softplus (TC tf32), packing {delta, u} float2 -> g_du
    tf32_gemm_v3<<<dim3(D_INNER / 128, MROWS / 128), 512, SMEM_BYTES>>>(
        MROWS, D_INNER, DT_RANK, dtin, DT_RANK, wdtt, DT_RANK, b_dt, du, 2, nullptr);

    // idx 9-10: single-pass chunked scan with decoupled look-back -> g_y
    zero_flags_kernel<<<(CHAINS * NC + 255) / 256, 256>>>();
    scan_fused<<<dim3(NC, D_INNER / DBLK, NBATCH), 256>>>(A_log, Dp);

    // idx 11: out_proj (TC tf32): out = g_y @ woutt^T
    tf32_gemm_v3<<<dim3(D_MODEL / 128, MROWS / 128), 512, SMEM_BYTES>>>(
        MROWS, D_MODEL, D_INNER, y, D_INNER, woutt, D_INNER, nullptr, out, 0, nullptr);
}